// round 15
// baseline (speedup 1.0000x reference)
#include <cuda_runtime.h>
#include <cuda_bf16.h>
#include <math.h>

typedef unsigned int u32;
typedef unsigned long long u64;
typedef __nv_bfloat16 bf;

#define BB 4
#define SS 1024
#define EE 512
#define NHH 8
#define DD 64
#define NTOK (BB*SS)          // 4096
#define TOKE ((long)NTOK*EE)  // 2,097,152
#define NB (BB*NHH)           // 32
#define NQKV 1536

#define WEE_B ((long)EE*EE)
#define WQKV_B ((long)NQKV*EE)
#define WFF_B ((long)EE*4*EE)
#define QKV_B ((long)NTOK*NQKV)
#define HID_B ((long)NTOK*4*EE)

// ------------------------- fp32 scratch ([2] = body, limb) -------------------------
__device__ float g_tmp[2*NTOK*EE];
__device__ float g_bl[2*NTOK*EE];
__device__ float g_cross[2*NTOK*EE];
__device__ float g_ffn[2*NTOK*EE];
__device__ float g_qkvb[4*NQKV];

// ------------------------- bf16 split scratch (16B aligned) -------------------------
__device__ __align__(16) bf g_xh[2*NTOK*EE], g_xl[2*NTOK*EE];
__device__ __align__(16) bf g_s1h[2*NTOK*EE], g_s1l[2*NTOK*EE];
__device__ __align__(16) bf g_qkvh[(long)2*NTOK*NQKV], g_qkvl[(long)2*NTOK*NQKV];
__device__ __align__(16) bf g_atth[2*NTOK*EE], g_attl[2*NTOK*EE];
__device__ __align__(16) bf g_hidh[(long)2*NTOK*4*EE], g_hidl[(long)2*NTOK*4*EE];
__device__ __align__(16) bf g_wqkvh[(long)4*NQKV*EE], g_wqkvl[(long)4*NQKV*EE];
__device__ __align__(16) bf g_owth[4*EE*EE], g_owtl[4*EE*EE];
__device__ __align__(16) bf g_w1th[(long)2*EE*4*EE], g_w1tl[(long)2*EE*4*EE];
__device__ __align__(16) bf g_w2th[(long)2*EE*4*EE], g_w2tl[(long)2*EE*4*EE];

// ------------------------- asm helpers -------------------------
__device__ __forceinline__ u32 s2u(const void* p) {
    u32 a;
    asm("{ .reg .u64 t; cvta.to.shared.u64 t, %1; cvt.u32.u64 %0, t; }" : "=r"(a) : "l"(p));
    return a;
}
__device__ __forceinline__ void cpa16(u32 saddr, const void* g) {
    asm volatile("cp.async.cg.shared.global [%0], [%1], 16;" :: "r"(saddr), "l"(g));
}
__device__ __forceinline__ void cpcommit() { asm volatile("cp.async.commit_group;"); }
__device__ __forceinline__ void cpwait0()  { asm volatile("cp.async.wait_group 0;"); }

__device__ __forceinline__ void ldsm_x4(u32 r[4], u32 addr) {
    asm volatile("ldmatrix.sync.aligned.m8n8.x4.shared.b16 {%0,%1,%2,%3}, [%4];"
                 : "=r"(r[0]), "=r"(r[1]), "=r"(r[2]), "=r"(r[3]) : "r"(addr));
}
__device__ __forceinline__ void ldsm_x4t(u32 r[4], u32 addr) {
    asm volatile("ldmatrix.sync.aligned.m8n8.x4.trans.shared.b16 {%0,%1,%2,%3}, [%4];"
                 : "=r"(r[0]), "=r"(r[1]), "=r"(r[2]), "=r"(r[3]) : "r"(addr));
}
__device__ __forceinline__ void mma16816(float c[4], const u32 a[4], const u32 b0, const u32 b1) {
    asm volatile(
        "mma.sync.aligned.m16n8k16.row.col.f32.bf16.bf16.f32 "
        "{%0,%1,%2,%3}, {%4,%5,%6,%7}, {%8,%9}, {%0,%1,%2,%3};"
        : "+f"(c[0]), "+f"(c[1]), "+f"(c[2]), "+f"(c[3])
        : "r"(a[0]), "r"(a[1]), "r"(a[2]), "r"(a[3]), "r"(b0), "r"(b1));
}
__device__ __forceinline__ void split2(float x, float y, u32& hp, u32& lp) {
    bf hx = __float2bfloat16(x), hy = __float2bfloat16(y);
    bf lx = __float2bfloat16(x - __bfloat162float(hx));
    bf ly = __float2bfloat16(y - __bfloat162float(hy));
    hp = (u32)__bfloat16_as_ushort(hx) | ((u32)__bfloat16_as_ushort(hy) << 16);
    lp = (u32)__bfloat16_as_ushort(lx) | ((u32)__bfloat16_as_ushort(ly) << 16);
}

// ------------------------- bf16-split tensor-core GEMM, cp.async pipelined -----
// 128 x 128 CTA tile (WN=64), 8 warps 4m x 2n. Single-sync pipeline:
// loads for chunk c+1 are issued AFTER the top barrier of chunk c, so the
// trailing barrier is unnecessary (top barrier of c proves compute c-1 done).
// Per batch z: C[i,j] = act(sum_l A[i,l]*B[j,l] + bias[j]).
// A-offset rule: column tiles with j0 < jsplit use z*aB; else aOff2 + z*aB2.
// OMODE: 0 fp32; 2 bf16 hi/lo.
template<int WN, int OMODE, bool GELU>
__global__ void __launch_bounds__(256) gemm_mma(
    const bf* __restrict__ Ah, const bf* __restrict__ Al,
    const bf* __restrict__ Bh, const bf* __restrict__ Bl,
    const float* __restrict__ bias, float* __restrict__ C,
    bf* __restrict__ Ch, bf* __restrict__ Cl,
    int K, int lda, int ldb, int ldc,
    long aB, long bB, long cB, long biasB,
    int jsplit, long aOff2, long aB2)
{
    constexpr int BN = 2 * WN;
    constexpr int STR = 40;
    constexpr int ASZ = 128 * STR;
    constexpr int BSZ = BN * STR;
    constexpr int STAGE = 2 * ASZ + 2 * BSZ;

    extern __shared__ __align__(16) bf sm[];

    int z = blockIdx.z;
    int j0 = blockIdx.x * BN;
    long aoff = (j0 < jsplit) ? z * aB : aOff2 + z * aB2;
    Ah += aoff;  Al += aoff;
    Bh += z * bB;  Bl += z * bB;
    if (bias) bias += z * biasB;
    long coff = z * cB;

    int i0 = blockIdx.y * 128;
    int tid = threadIdx.x;
    int lane = tid & 31, wid = tid >> 5;
    int wm = wid & 3, wn = wid >> 2;

    float acc[2][WN / 8][4] = {};
    const int nch = K / 32;

    auto load_stage = [&](int c, int s) {
        long kc = (long)c * 32;
        u32 base = s2u(sm + s * STAGE);
        #pragma unroll
        for (int t = 0; t < 2; t++) {
            int idx = tid + t * 256;
            int r = idx >> 2, sg = idx & 3;
            long go = (long)(i0 + r) * lda + kc + sg * 8;
            u32 so = (u32)(r * STR + sg * 8) * 2;
            cpa16(base + so, Ah + go);
            cpa16(base + ASZ * 2 + so, Al + go);
        }
        #pragma unroll
        for (int t = 0; t < BN / 64; t++) {
            int idx = tid + t * 256;
            int r = idx >> 2, sg = idx & 3;
            long go = (long)(j0 + r) * ldb + kc + sg * 8;
            u32 so = (u32)(r * STR + sg * 8) * 2;
            cpa16(base + 4 * ASZ + so, Bh + go);
            cpa16(base + 4 * ASZ + 2 * BSZ + so, Bl + go);
        }
    };

    load_stage(0, 0);
    cpcommit();

    for (int c = 0; c < nch; c++) {
        cpwait0();
        __syncthreads();
        if (c + 1 < nch) {
            load_stage(c + 1, (c + 1) & 1);
            cpcommit();
        }

        const bf* sAh = sm + (c & 1) * STAGE;
        const bf* sAl = sAh + ASZ;
        const bf* sBh = sAl + ASZ;
        const bf* sBl = sBh + BSZ;

        #pragma unroll
        for (int ks = 0; ks < 2; ks++) {
            u32 afh[2][4], afl[2][4];
            #pragma unroll
            for (int mt = 0; mt < 2; mt++) {
                int row = wm * 32 + mt * 16 + (lane & 15);
                int col = ks * 16 + (lane >> 4) * 8;
                ldsm_x4(afh[mt], s2u(&sAh[row * STR + col]));
                ldsm_x4(afl[mt], s2u(&sAl[row * STR + col]));
            }
            int sel = lane >> 3;
            #pragma unroll
            for (int np = 0; np < WN / 16; np++) {
                int brow = wn * WN + (np * 2 + (sel >> 1)) * 8 + (lane & 7);
                int bcol = ks * 16 + (sel & 1) * 8;
                u32 bh4[4], bl4[4];
                ldsm_x4(bh4, s2u(&sBh[brow * STR + bcol]));
                ldsm_x4(bl4, s2u(&sBl[brow * STR + bcol]));
                #pragma unroll
                for (int q = 0; q < 2; q++) {
                    int nt = np * 2 + q;
                    #pragma unroll
                    for (int mt = 0; mt < 2; mt++) {
                        mma16816(acc[mt][nt], afh[mt], bh4[2 * q], bh4[2 * q + 1]);
                        mma16816(acc[mt][nt], afh[mt], bl4[2 * q], bl4[2 * q + 1]);
                        mma16816(acc[mt][nt], afl[mt], bh4[2 * q], bh4[2 * q + 1]);
                    }
                }
            }
        }
    }

    int grp = lane >> 2, qd = lane & 3;
    #pragma unroll
    for (int mt = 0; mt < 2; mt++) {
        #pragma unroll
        for (int nt = 0; nt < WN / 8; nt++) {
            int n = j0 + wn * WN + nt * 8 + qd * 2;
            float b0 = 0.f, b1 = 0.f;
            if (bias) { b0 = bias[n]; b1 = bias[n + 1]; }
            #pragma unroll
            for (int rh = 0; rh < 2; rh++) {
                int m = i0 + wm * 32 + mt * 16 + grp + rh * 8;
                float x = acc[mt][nt][rh * 2 + 0] + b0;
                float y = acc[mt][nt][rh * 2 + 1] + b1;
                if (GELU) {
                    x = 0.5f * x * (1.f + erff(x * 0.70710678118654752f));
                    y = 0.5f * y * (1.f + erff(y * 0.70710678118654752f));
                }
                long off = coff + (long)m * ldc + n;
                if (OMODE == 0) {
                    *(float2*)&C[off] = make_float2(x, y);
                } else {
                    u32 hp, lp;
                    split2(x, y, hp, lp);
                    *(u32*)&Ch[off] = hp;
                    *(u32*)&Cl[off] = lp;
                }
            }
        }
    }
}

// ------------------------- flash attention (packed QKV, 2 streams) -------------------------
#define KVT 64
#define FSTR 72
#define FQSZ (128 * FSTR)
#define FKSZ (KVT * FSTR)
#define FSTG (4 * FKSZ)
#define FSMEM ((2 * FQSZ + 2 * FSTG) * 2)   // 110,592 B

__global__ void __launch_bounds__(256) flash_k(
    const bf* __restrict__ QKVh, const bf* __restrict__ QKVl,
    bf* __restrict__ Oh, bf* __restrict__ Ol,
    const unsigned* __restrict__ tptr)
{
    extern __shared__ __align__(16) bf fsm[];
    bf* sQh = fsm;
    bf* sQl = fsm + FQSZ;
    bf* stg = fsm + 2 * FQSZ;

    int q0 = blockIdx.x * 128;
    int y = blockIdx.y;
    int strm = y >> 5;
    int z = y & 31;
    int b = z / NHH, h = z - b * NHH;
    long qbase = (long)strm * NTOK * NQKV + (long)b * SS * NQKV + h * DD;
    long obase = (long)strm * TOKE + (long)b * SS * EE;

    int tid = threadIdx.x, lane = tid & 31, w = tid >> 5;
    int grp = lane >> 2, qd = lane & 3;
    int sel = lane >> 3;

    #pragma unroll
    for (int t = 0; t < 4; t++) {
        int idx = tid + t * 256;
        int r = idx >> 3, sg = idx & 7;
        long go = qbase + (long)(q0 + r) * NQKV + sg * 8;
        u32 so = (u32)(r * FSTR + sg * 8) * 2;
        cpa16(s2u(sQh) + so, QKVh + go);
        cpa16(s2u(sQl) + so, QKVl + go);
    }
    auto load_kv = [&](int c, int s) {
        bf* st = stg + s * FSTG;
        int kv0 = c * KVT;
        #pragma unroll
        for (int t = 0; t < 2; t++) {
            int idx = tid + t * 256;
            int r = idx >> 3, sg = idx & 7;
            u32 so = (u32)(r * FSTR + sg * 8) * 2;
            long gk = qbase + 512 + (long)(kv0 + r) * NQKV + sg * 8;
            cpa16(s2u(st) + so, QKVh + gk);
            cpa16(s2u(st + FKSZ) + so, QKVl + gk);
            long gv = qbase + 1024 + (long)(kv0 + r) * NQKV + sg * 8;
            cpa16(s2u(st + 2 * FKSZ) + so, QKVh + gv);
            cpa16(s2u(st + 3 * FKSZ) + so, QKVl + gv);
        }
    };
    load_kv(0, 0);
    cpcommit();

    float scl;
    {
        unsigned u = *tptr;
        float f = __uint_as_float(u);
        float temp = (f > 1e-6f && f < 1e6f) ? f : (float)(int)u;
        scl = 0.125f / temp;
    }

    float m0 = -1e30f, m1 = -1e30f, l0 = 0.f, l1 = 0.f;
    float acc_o[8][4] = {};

    const int NT = SS / KVT;
    for (int c = 0; c < NT; c++) {
        cpwait0();
        __syncthreads();
        if (c + 1 < NT) {
            load_kv(c + 1, (c + 1) & 1);
            cpcommit();
        }
        bf* st = stg + (c & 1) * FSTG;
        bf* sKh = st;
        bf* sKl = st + FKSZ;
        bf* sVh = st + 2 * FKSZ;
        bf* sVl = st + 3 * FKSZ;

        float s_[8][4] = {};
        #pragma unroll
        for (int t = 0; t < 4; t++) {
            u32 ah4[4], al4[4];
            int arow = w * 16 + (lane & 15);
            int acol = t * 16 + (lane >> 4) * 8;
            ldsm_x4(ah4, s2u(&sQh[arow * FSTR + acol]));
            ldsm_x4(al4, s2u(&sQl[arow * FSTR + acol]));
            #pragma unroll
            for (int jp = 0; jp < 4; jp++) {
                int brow = (jp * 2 + (sel >> 1)) * 8 + (lane & 7);
                int bcol = t * 16 + (sel & 1) * 8;
                u32 bh4[4], bl4[4];
                ldsm_x4(bh4, s2u(&sKh[brow * FSTR + bcol]));
                ldsm_x4(bl4, s2u(&sKl[brow * FSTR + bcol]));
                #pragma unroll
                for (int q = 0; q < 2; q++) {
                    int j = jp * 2 + q;
                    mma16816(s_[j], ah4, bh4[2 * q], bh4[2 * q + 1]);
                    mma16816(s_[j], ah4, bl4[2 * q], bl4[2 * q + 1]);
                    mma16816(s_[j], al4, bh4[2 * q], bh4[2 * q + 1]);
                }
            }
        }
        float t0 = -1e30f, t1 = -1e30f;
        #pragma unroll
        for (int j = 0; j < 8; j++) {
            s_[j][0] *= scl; s_[j][1] *= scl; s_[j][2] *= scl; s_[j][3] *= scl;
            t0 = fmaxf(t0, fmaxf(s_[j][0], s_[j][1]));
            t1 = fmaxf(t1, fmaxf(s_[j][2], s_[j][3]));
        }
        t0 = fmaxf(t0, __shfl_xor_sync(0xffffffffu, t0, 1));
        t0 = fmaxf(t0, __shfl_xor_sync(0xffffffffu, t0, 2));
        t1 = fmaxf(t1, __shfl_xor_sync(0xffffffffu, t1, 1));
        t1 = fmaxf(t1, __shfl_xor_sync(0xffffffffu, t1, 2));
        float nm0 = fmaxf(m0, t0), nm1 = fmaxf(m1, t1);
        float corr0 = __expf(m0 - nm0), corr1 = __expf(m1 - nm1);
        m0 = nm0; m1 = nm1;
        float sum0 = 0.f, sum1 = 0.f;
        #pragma unroll
        for (int j = 0; j < 8; j++) {
            s_[j][0] = __expf(s_[j][0] - m0);
            s_[j][1] = __expf(s_[j][1] - m0);
            s_[j][2] = __expf(s_[j][2] - m1);
            s_[j][3] = __expf(s_[j][3] - m1);
            sum0 += s_[j][0] + s_[j][1];
            sum1 += s_[j][2] + s_[j][3];
        }
        sum0 += __shfl_xor_sync(0xffffffffu, sum0, 1);
        sum0 += __shfl_xor_sync(0xffffffffu, sum0, 2);
        sum1 += __shfl_xor_sync(0xffffffffu, sum1, 1);
        sum1 += __shfl_xor_sync(0xffffffffu, sum1, 2);
        l0 = l0 * corr0 + sum0;
        l1 = l1 * corr1 + sum1;
        #pragma unroll
        for (int n = 0; n < 8; n++) {
            acc_o[n][0] *= corr0; acc_o[n][1] *= corr0;
            acc_o[n][2] *= corr1; acc_o[n][3] *= corr1;
        }
        #pragma unroll
        for (int t = 0; t < 4; t++) {
            u32 pah[4], pal[4];
            split2(s_[2 * t][0],     s_[2 * t][1],     pah[0], pal[0]);
            split2(s_[2 * t][2],     s_[2 * t][3],     pah[1], pal[1]);
            split2(s_[2 * t + 1][0], s_[2 * t + 1][1], pah[2], pal[2]);
            split2(s_[2 * t + 1][2], s_[2 * t + 1][3], pah[3], pal[3]);
            int vrow = t * 16 + (lane & 15);
            #pragma unroll
            for (int np = 0; np < 4; np++) {
                int vcol = (np * 2 + (lane >> 4)) * 8;
                u32 bh4[4], bl4[4];
                ldsm_x4t(bh4, s2u(&sVh[vrow * FSTR + vcol]));
                ldsm_x4t(bl4, s2u(&sVl[vrow * FSTR + vcol]));
                #pragma unroll
                for (int q = 0; q < 2; q++) {
                    int n = np * 2 + q;
                    mma16816(acc_o[n], pah, bh4[2 * q], bh4[2 * q + 1]);
                    mma16816(acc_o[n], pah, bl4[2 * q], bl4[2 * q + 1]);
                    mma16816(acc_o[n], pal, bh4[2 * q], bh4[2 * q + 1]);
                }
            }
        }
    }

    float inv0 = 1.f / l0, inv1 = 1.f / l1;
    int r0 = q0 + w * 16 + grp;
    #pragma unroll
    for (int n = 0; n < 8; n++) {
        int col = h * DD + n * 8 + qd * 2;
        {
            long off = obase + (long)r0 * EE + col;
            u32 hp, lp;
            split2(acc_o[n][0] * inv0, acc_o[n][1] * inv0, hp, lp);
            *(u32*)&Oh[off] = hp;
            *(u32*)&Ol[off] = lp;
        }
        {
            long off = obase + (long)(r0 + 8) * EE + col;
            u32 hp, lp;
            split2(acc_o[n][2] * inv1, acc_o[n][3] * inv1, hp, lp);
            *(u32*)&Oh[off] = hp;
            *(u32*)&Ol[off] = lp;
        }
    }
}

// ------------------------- ONE-launch preprocessing -------------------------
__global__ void prep_k(const float* __restrict__ qw, const float* __restrict__ kw,
                       const float* __restrict__ vw, const float* __restrict__ ow,
                       const float* __restrict__ w1, const float* __restrict__ w2,
                       const float* __restrict__ qb, const float* __restrict__ kb,
                       const float* __restrict__ vb,
                       const float* __restrict__ in0, const float* __restrict__ in1)
{
    int t = blockIdx.x;
    int tx = threadIdx.x, ty = threadIdx.y;
    int ltid = ty * 32 + tx;

    if (t >= 8200) {
        int idx = t - 8200;
        int strm = idx >> 11;
        long i = (long)(idx & 2047) * 1024 + ltid * 4;
        const float* x = strm ? in1 : in0;
        float4 v = *(const float4*)(x + i);
        u32 hp[2], lp[2];
        split2(v.x, v.y, hp[0], lp[0]);
        split2(v.z, v.w, hp[1], lp[1]);
        long o = (long)strm * TOKE + i;
        *(uint2*)(g_xh + o) = make_uint2(hp[0], hp[1]);
        *(uint2*)(g_xl + o) = make_uint2(lp[0], lp[1]);
        return;
    }
    if (t >= 8192) {
        int blk = t - 8192;
        int i = blk >> 1;
        int tt = (blk & 1) * 256 + ltid;
        g_qkvb[i * NQKV + tt]        = qb[i * EE + tt];
        g_qkvb[i * NQKV + 512 + tt]  = kb[i * EE + tt];
        g_qkvb[i * NQKV + 1024 + tt] = vb[i * EE + tt];
        return;
    }

    __shared__ float sm[32][33];
    const float* src;
    bf *dh, *dl;
    int lds, ldd, ry, cx;

    if (t < 4096) {
        int g = t >> 10, rem = t & 1023;
        int b = rem >> 8, tt = rem & 255;
        ry = tt >> 4; cx = tt & 15;
        lds = 512; ldd = 512;
        const float* s4 = (g == 0) ? qw : (g == 1) ? kw : (g == 2) ? vw : ow;
        src = s4 + (long)b * WEE_B;
        if (g < 3) {
            dh = g_wqkvh + (long)b * WQKV_B + (long)g * 512 * EE;
            dl = g_wqkvl + (long)b * WQKV_B + (long)g * 512 * EE;
        } else {
            dh = g_owth + (long)b * WEE_B;
            dl = g_owtl + (long)b * WEE_B;
        }
    } else if (t < 6144) {
        int t2 = t - 4096;
        int b = t2 >> 10, tt = t2 & 1023;
        ry = tt >> 6; cx = tt & 63;
        lds = 2048; ldd = 512;
        src = w1 + (long)b * WFF_B;
        dh = g_w1th + (long)b * WFF_B;
        dl = g_w1tl + (long)b * WFF_B;
    } else {
        int t3 = t - 6144;
        int b = t3 >> 10, tt = t3 & 1023;
        ry = tt >> 4; cx = tt & 15;
        lds = 512; ldd = 2048;
        src = w2 + (long)b * WFF_B;
        dh = g_w2th + (long)b * WFF_B;
        dl = g_w2tl + (long)b * WFF_B;
    }

    int r0 = ry * 32, c0 = cx * 32;
    #pragma unroll
    for (int i = 0; i < 4; i++)
        sm[ty + 8 * i][tx] = src[(long)(r0 + ty + 8 * i) * lds + c0 + tx];
    __syncthreads();
    #pragma unroll
    for (int i = 0; i < 4; i++) {
        int n = c0 + ty + 8 * i, k = r0 + tx;
        float v = sm[tx][ty + 8 * i];
        bf hv = __float2bfloat16(v);
        bf lv = __float2bfloat16(v - __bfloat162float(hv));
        dh[(long)n * ldd + k] = hv;
        dl[(long)n * ldd + k] = lv;
    }
}

// ------------------------- batched residual + layernorm (+ optional split out) -----
__global__ void ln2_k(const float* __restrict__ x0, const float* __restrict__ x1,
                      const float* __restrict__ res,
                      const float* __restrict__ g0, const float* __restrict__ b0_,
                      const float* __restrict__ g1, const float* __restrict__ b1_,
                      float* __restrict__ out,
                      bf* __restrict__ oh = nullptr,
                      bf* __restrict__ ol = nullptr)
{
    long row = blockIdx.x;
    int strm = row >= NTOK;
    long r = row - (long)strm * NTOK;
    const float* x = (strm ? x1 : x0) + r * EE;
    const float* gamma = strm ? g1 : g0;
    const float* beta  = strm ? b1_ : b0_;
    int t = threadIdx.x;
    float4 v = ((const float4*)x)[t];
    if (res) {
        float4 rr = ((const float4*)(res + row * EE))[t];
        v.x += rr.x; v.y += rr.y; v.z += rr.z; v.w += rr.w;
    }
    float s = v.x + v.y + v.z + v.w;
    float q = v.x * v.x + v.y * v.y + v.z * v.z + v.w * v.w;
    #pragma unroll
    for (int o = 16; o; o >>= 1) {
        s += __shfl_xor_sync(0xffffffffu, s, o);
        q += __shfl_xor_sync(0xffffffffu, q, o);
    }
    __shared__ float shS[4], shQ[4];
    int w = t >> 5;
    if ((t & 31) == 0) { shS[w] = s; shQ[w] = q; }
    __syncthreads();
    s = shS[0] + shS[1] + shS[2] + shS[3];
    q = shQ[0] + shQ[1] + shQ[2] + shQ[3];
    float mean = s * (1.f / EE);
    float var = q * (1.f / EE) - mean * mean;
    float rstd = rsqrtf(var + 1e-5f);
    float4 g = ((const float4*)gamma)[t];
    float4 b = ((const float4*)beta)[t];
    float4 o;
    o.x = (v.x - mean) * rstd * g.x + b.x;
    o.y = (v.y - mean) * rstd * g.y + b.y;
    o.z = (v.z - mean) * rstd * g.z + b.z;
    o.w = (v.w - mean) * rstd * g.w + b.w;
    ((float4*)(out + row * EE))[t] = o;
    if (oh) {
        u32 hp[2], lp[2];
        split2(o.x, o.y, hp[0], lp[0]);
        split2(o.z, o.w, hp[1], lp[1]);
        *(uint2*)(oh + row * EE + t * 4) = make_uint2(hp[0], hp[1]);
        *(uint2*)(ol + row * EE + t * 4) = make_uint2(lp[0], lp[1]);
    }
}

// ------------------------- fused gate + mix + norm2 (gamma shared) -------------------------
__global__ void gate_mix_ln_k(const float* __restrict__ x, const float* __restrict__ cr,
                              const float* __restrict__ gw, const float* __restrict__ gb,
                              const float* __restrict__ gamma, const float* __restrict__ beta,
                              float* __restrict__ out,
                              bf* __restrict__ oh, bf* __restrict__ ol)
{
    long row = blockIdx.x;
    int t = threadIdx.x;
    float4 xv = ((const float4*)(x + row * EE))[t];
    float4 cv = ((const float4*)(cr + row * EE))[t];
    int k0 = t * 4;
    float l0 = 0.f, l1 = 0.f;
    float xs[4] = {xv.x, xv.y, xv.z, xv.w};
    float cs[4] = {cv.x, cv.y, cv.z, cv.w};
    #pragma unroll
    for (int e = 0; e < 4; e++) {
        int k = k0 + e;
        l0 += xs[e] * gw[k * 2 + 0] + cs[e] * gw[(EE + k) * 2 + 0];
        l1 += xs[e] * gw[k * 2 + 1] + cs[e] * gw[(EE + k) * 2 + 1];
    }
    #pragma unroll
    for (int o = 16; o; o >>= 1) {
        l0 += __shfl_xor_sync(0xffffffffu, l0, o);
        l1 += __shfl_xor_sync(0xffffffffu, l1, o);
    }
    __shared__ float sh0[4], sh1[4];
    int w = t >> 5;
    if ((t & 31) == 0) { sh0[w] = l0; sh1[w] = l1; }
    __syncthreads();
    l0 = sh0[0] + sh0[1] + sh0[2] + sh0[3] + gb[0];
    l1 = sh1[0] + sh1[1] + sh1[2] + sh1[3] + gb[1];
    float mx = fmaxf(l0, l1);
    float e0 = __expf(l0 - mx), e1 = __expf(l1 - mx);
    float gg0 = e0 / (e0 + e1), gg1 = e1 / (e0 + e1);
    float4 v;
    v.x = xv.x * gg0 + cv.x * gg1;
    v.y = xv.y * gg0 + cv.y * gg1;
    v.z = xv.z * gg0 + cv.z * gg1;
    v.w = xv.w * gg0 + cv.w * gg1;

    float s = v.x + v.y + v.z + v.w;
    float q = v.x * v.x + v.y * v.y + v.z * v.z + v.w * v.w;
    #pragma unroll
    for (int o = 16; o; o >>= 1) {
        s += __shfl_xor_sync(0xffffffffu, s, o);
        q += __shfl_xor_sync(0xffffffffu, q, o);
    }
    __syncthreads();
    if ((t & 31) == 0) { sh0[w] = s; sh1[w] = q; }
    __syncthreads();
    s = sh0[0] + sh0[1] + sh0[2] + sh0[3];
    q = sh1[0] + sh1[1] + sh1[2] + sh1[3];
    float mean = s * (1.f / EE);
    float var = q * (1.f / EE) - mean * mean;
    float rstd = rsqrtf(var + 1e-5f);
    float4 g = ((const float4*)gamma)[t];
    float4 b = ((const float4*)beta)[t];
    float4 o;
    o.x = (v.x - mean) * rstd * g.x + b.x;
    o.y = (v.y - mean) * rstd * g.y + b.y;
    o.z = (v.z - mean) * rstd * g.z + b.z;
    o.w = (v.w - mean) * rstd * g.w + b.w;
    ((float4*)(out + row * EE))[t] = o;
    u32 hp[2], lp[2];
    split2(o.x, o.y, hp[0], lp[0]);
    split2(o.z, o.w, hp[1], lp[1]);
    *(uint2*)(oh + row * EE + t * 4) = make_uint2(hp[0], hp[1]);
    *(uint2*)(ol + row * EE + t * 4) = make_uint2(lp[0], lp[1]);
}

// ------------------------- host orchestration -------------------------
static float* sym(const void* s) { void* p = nullptr; cudaGetSymbolAddress(&p, s); return (float*)p; }
static bf* symb(const void* s)   { void* p = nullptr; cudaGetSymbolAddress(&p, s); return (bf*)p; }

#define SMEM64 ((2 * 128 * 40 + 2 * 128 * 40) * 2 * 2)   // 81920 B
#define JBIG (1 << 30)

static void bg_f32(const bf* ah, const bf* al, const bf* bh, const bf* bl, long aB, long bB,
                   const float* bias, long biasB, float* C, long cB, int M, int N, int K, int ldc) {
    dim3 grid(N / 128, M / 128, 2);
    gemm_mma<64, 0, false><<<grid, 256, SMEM64>>>(ah, al, bh, bl, bias, C, nullptr, nullptr,
        K, K, K, ldc, aB, bB, cB, biasB, JBIG, 0, 0);
}
static void bg_sp(const bf* ah, const bf* al, const bf* bh, const bf* bl, long aB, long bB,
                  const float* bias, long biasB, bf* Ch, bf* Cl, long cB,
                  int M, int N, int K, int ldc, bool gelu,
                  int jsplit = JBIG, long aOff2 = 0, long aB2 = 0) {
    dim3 grid(N / 128, M / 128, 2);
    if (gelu)
        gemm_mma<64, 2, true><<<grid, 256, SMEM64>>>(ah, al, bh, bl, bias, nullptr, Ch, Cl,
            K, K, K, ldc, aB, bB, cB, biasB, jsplit, aOff2, aB2);
    else
        gemm_mma<64, 2, false><<<grid, 256, SMEM64>>>(ah, al, bh, bl, bias, nullptr, Ch, Cl,
            K, K, K, ldc, aB, bB, cB, biasB, jsplit, aOff2, aB2);
}

extern "C" void kernel_launch(void* const* d_in, const int* in_sizes, int n_in,
                              void* d_out, int out_size)
{
    const float* body_feats = (const float*)d_in[0];
    const float* limb_feats = (const float*)d_in[1];
    const float* attn_qw = (const float*)d_in[2];
    const float* attn_qb = (const float*)d_in[3];
    const float* attn_kw = (const float*)d_in[4];
    const float* attn_kb = (const float*)d_in[5];
    const float* attn_vw = (const float*)d_in[6];
    const float* attn_vb = (const float*)d_in[7];
    const float* attn_ow = (const float*)d_in[8];
    const float* attn_ob = (const float*)d_in[9];
    const float* ffn_w1 = (const float*)d_in[10];
    const float* ffn_b1 = (const float*)d_in[11];
    const float* ffn_w2 = (const float*)d_in[12];
    const float* ffn_b2 = (const float*)d_in[13];
    const float* nsc = (const float*)d_in[14];
    const float* nbi = (const float*)d_in[15];
    const float* gw = (const float*)d_in[16];
    const float* gb = (const float*)d_in[17];
    const unsigned* temp = (const unsigned*)d_in[18];

    cudaFuncSetAttribute(gemm_mma<64, 0, false>, cudaFuncAttributeMaxDynamicSharedMemorySize, SMEM64);
    cudaFuncSetAttribute(gemm_mma<64, 2, false>, cudaFuncAttributeMaxDynamicSharedMemorySize, SMEM64);
    cudaFuncSetAttribute(gemm_mma<64, 2, true>,  cudaFuncAttributeMaxDynamicSharedMemorySize, SMEM64);
    cudaFuncSetAttribute(flash_k, cudaFuncAttributeMaxDynamicSharedMemorySize, FSMEM);

    float* out = (float*)d_out;

    float* tmp  = sym(g_tmp);
    float* bl   = sym(g_bl);
    float* cross = sym(g_cross);
    float* ffn  = sym(g_ffn);
    bf *xh = symb(g_xh), *xl = symb(g_xl);
    bf *s1h = symb(g_s1h), *s1l = symb(g_s1l);
    bf *qkvh = symb(g_qkvh), *qkvl = symb(g_qkvl);
    bf *atth = symb(g_atth), *attl = symb(g_attl);
    bf *hidh = symb(g_hidh), *hidl = symb(g_hidl);
    bf *wqh = symb(g_wqkvh), *wql = symb(g_wqkvl);
    bf *owh = symb(g_owth), *owl = symb(g_owtl);
    bf *w1h = symb(g_w1th), *w1l = symb(g_w1tl);
    bf *w2h = symb(g_w2th), *w2l = symb(g_w2tl);
    const float* qkvb = sym(g_qkvb);

    // ---- preprocessing (ONE launch) ----
    prep_k<<<12296, dim3(32, 8)>>>(attn_qw, attn_kw, attn_vw, attn_ow, ffn_w1, ffn_w2,
                                   attn_qb, attn_kb, attn_vb, body_feats, limb_feats);

    // ---- self attention (batched over body/limb) ----
    bg_sp(xh, xl, wqh, wql, TOKE, WQKV_B, qkvb, NQKV,
          qkvh, qkvl, QKV_B, NTOK, NQKV, EE, NQKV, false);
    flash_k<<<dim3(SS / 128, 2 * NB), 256, FSMEM>>>(qkvh, qkvl, atth, attl, temp);
    bg_f32(atth, attl, owh, owl, TOKE, WEE_B, attn_ob, EE, tmp, TOKE, NTOK, EE, EE, EE);

    // norm1 (batched): body gamma 0, limb gamma 3
    ln2_k<<<2 * NTOK, 128>>>(body_feats, limb_feats, tmp,
                             nsc + 0 * EE, nbi + 0 * EE, nsc + 3 * EE, nbi + 3 * EE,
                             bl, s1h, s1l);

    // ---- cross attention: ONE fused QKV launch ----
    bg_sp(s1h, s1l, wqh + 2 * WQKV_B, wql + 2 * WQKV_B, TOKE, WQKV_B,
          qkvb + 2 * NQKV, NQKV, qkvh, qkvl, QKV_B, NTOK, NQKV, EE, NQKV, false,
          /*jsplit=*/512, /*aOff2=*/TOKE, /*aB2=*/-TOKE);
    flash_k<<<dim3(SS / 128, 2 * NB), 256, FSMEM>>>(qkvh, qkvl, atth, attl, temp);
    bg_f32(atth, attl, owh + 2 * WEE_B, owl + 2 * WEE_B, TOKE, WEE_B,
           attn_ob + 2 * EE, EE, cross, TOKE, NTOK, EE, EE, EE);

    // ---- fused gate + mix + norm2 (gamma 1 on BOTH streams — faithful) ----
    gate_mix_ln_k<<<2 * NTOK, 128>>>(bl, cross, gw, gb,
                                     nsc + 1 * EE, nbi + 1 * EE, bl, s1h, s1l);

    // ---- FFN (batched) ----
    bg_sp(s1h, s1l, w1h, w1l, TOKE, WFF_B, ffn_b1, 4 * EE,
          hidh, hidl, HID_B, NTOK, 4 * EE, EE, 4 * EE, true);
    bg_f32(hidh, hidl, w2h, w2l, HID_B, WFF_B, ffn_b2, EE, ffn, TOKE, NTOK, EE, 4 * EE, EE);

    // final norms (batched): body gamma 2, limb gamma 5 -> out
    ln2_k<<<2 * NTOK, 128>>>(bl, bl + TOKE, ffn,
                             nsc + 2 * EE, nbi + 2 * EE, nsc + 5 * EE, nbi + 5 * EE,
                             out, nullptr, nullptr);
}

// round 16
// speedup vs baseline: 1.0912x; 1.0912x over previous
#include <cuda_runtime.h>
#include <cuda_bf16.h>
#include <math.h>

typedef unsigned int u32;
typedef unsigned long long u64;
typedef __nv_bfloat16 bf;

#define BB 4
#define SS 1024
#define EE 512
#define NHH 8
#define DD 64
#define NTOK (BB*SS)          // 4096
#define TOKE ((long)NTOK*EE)  // 2,097,152
#define NB (BB*NHH)           // 32
#define NQKV 1536

#define WEE_B ((long)EE*EE)
#define WQKV_B ((long)NQKV*EE)
#define WFF_B ((long)EE*4*EE)
#define QKV_B ((long)NTOK*NQKV)
#define HID_B ((long)NTOK*4*EE)

// ------------------------- fp32 scratch ([2] = body, limb) -------------------------
__device__ float g_tmp[2*NTOK*EE];
__device__ float g_bl[2*NTOK*EE];
__device__ float g_cross[2*NTOK*EE];
__device__ float g_ffn[2*NTOK*EE];
__device__ float g_qkvb[4*NQKV];

// ------------------------- bf16 split scratch (16B aligned) -------------------------
__device__ __align__(16) bf g_xh[2*NTOK*EE], g_xl[2*NTOK*EE];
__device__ __align__(16) bf g_s1h[2*NTOK*EE], g_s1l[2*NTOK*EE];
__device__ __align__(16) bf g_qkvh[(long)2*NTOK*NQKV], g_qkvl[(long)2*NTOK*NQKV];
__device__ __align__(16) bf g_atth[2*NTOK*EE], g_attl[2*NTOK*EE];
__device__ __align__(16) bf g_hidh[(long)2*NTOK*4*EE], g_hidl[(long)2*NTOK*4*EE];
__device__ __align__(16) bf g_wqkvh[(long)4*NQKV*EE], g_wqkvl[(long)4*NQKV*EE];
__device__ __align__(16) bf g_owth[4*EE*EE], g_owtl[4*EE*EE];
__device__ __align__(16) bf g_w1th[(long)2*EE*4*EE], g_w1tl[(long)2*EE*4*EE];
__device__ __align__(16) bf g_w2th[(long)2*EE*4*EE], g_w2tl[(long)2*EE*4*EE];

// ------------------------- asm helpers -------------------------
__device__ __forceinline__ u32 s2u(const void* p) {
    u32 a;
    asm("{ .reg .u64 t; cvta.to.shared.u64 t, %1; cvt.u32.u64 %0, t; }" : "=r"(a) : "l"(p));
    return a;
}
__device__ __forceinline__ void cpa16(u32 saddr, const void* g) {
    asm volatile("cp.async.cg.shared.global [%0], [%1], 16;" :: "r"(saddr), "l"(g));
}
__device__ __forceinline__ void cpcommit() { asm volatile("cp.async.commit_group;"); }
__device__ __forceinline__ void cpwait1()  { asm volatile("cp.async.wait_group 1;"); }
__device__ __forceinline__ void cpwait0()  { asm volatile("cp.async.wait_group 0;"); }

__device__ __forceinline__ void ldsm_x4(u32 r[4], u32 addr) {
    asm volatile("ldmatrix.sync.aligned.m8n8.x4.shared.b16 {%0,%1,%2,%3}, [%4];"
                 : "=r"(r[0]), "=r"(r[1]), "=r"(r[2]), "=r"(r[3]) : "r"(addr));
}
__device__ __forceinline__ void ldsm_x4t(u32 r[4], u32 addr) {
    asm volatile("ldmatrix.sync.aligned.m8n8.x4.trans.shared.b16 {%0,%1,%2,%3}, [%4];"
                 : "=r"(r[0]), "=r"(r[1]), "=r"(r[2]), "=r"(r[3]) : "r"(addr));
}
__device__ __forceinline__ void mma16816(float c[4], const u32 a[4], const u32 b0, const u32 b1) {
    asm volatile(
        "mma.sync.aligned.m16n8k16.row.col.f32.bf16.bf16.f32 "
        "{%0,%1,%2,%3}, {%4,%5,%6,%7}, {%8,%9}, {%0,%1,%2,%3};"
        : "+f"(c[0]), "+f"(c[1]), "+f"(c[2]), "+f"(c[3])
        : "r"(a[0]), "r"(a[1]), "r"(a[2]), "r"(a[3]), "r"(b0), "r"(b1));
}
__device__ __forceinline__ void split2(float x, float y, u32& hp, u32& lp) {
    bf hx = __float2bfloat16(x), hy = __float2bfloat16(y);
    bf lx = __float2bfloat16(x - __bfloat162float(hx));
    bf ly = __float2bfloat16(y - __bfloat162float(hy));
    hp = (u32)__bfloat16_as_ushort(hx) | ((u32)__bfloat16_as_ushort(hy) << 16);
    lp = (u32)__bfloat16_as_ushort(lx) | ((u32)__bfloat16_as_ushort(ly) << 16);
}

// ------------------------- bf16-split tensor-core GEMM, cp.async pipelined -----
// 128x128 tile (WN=64), 8 warps 4m x 2n, dual-sync 2-stage pipeline (R13 proven).
// NSPLIT: split-K factor. NSPLIT=2 -> grid.z = 2*2; partial sums combined by
// atomicAdd into pre-zeroed fp32 C (2 addends -> bit-deterministic).
// A-offset rule: column tiles with j0 < jsplit use z*aB; else aOff2 + z*aB2.
// OMODE: 0 fp32; 2 bf16 hi/lo (NSPLIT must be 1).
template<int WN, int OMODE, bool GELU, int NSPLIT>
__global__ void __launch_bounds__(256, 2) gemm_mma(
    const bf* __restrict__ Ah, const bf* __restrict__ Al,
    const bf* __restrict__ Bh, const bf* __restrict__ Bl,
    const float* __restrict__ bias, float* __restrict__ C,
    bf* __restrict__ Ch, bf* __restrict__ Cl,
    int K, int lda, int ldb, int ldc,
    long aB, long bB, long cB, long biasB,
    int jsplit, long aOff2, long aB2)
{
    constexpr int BN = 2 * WN;
    constexpr int STR = 40;
    constexpr int ASZ = 128 * STR;
    constexpr int BSZ = BN * STR;
    constexpr int STAGE = 2 * ASZ + 2 * BSZ;

    extern __shared__ __align__(16) bf sm[];

    int z = blockIdx.z / NSPLIT;
    int ksp = blockIdx.z % NSPLIT;
    int j0 = blockIdx.x * BN;
    long aoff = (j0 < jsplit) ? z * aB : aOff2 + z * aB2;
    long kc0 = (long)ksp * (K / NSPLIT);
    Ah += aoff;  Al += aoff;
    Bh += z * bB;  Bl += z * bB;
    if (bias) bias += z * biasB;
    if (NSPLIT > 1 && ksp != 0) bias = nullptr;
    long coff = z * cB;

    int i0 = blockIdx.y * 128;
    int tid = threadIdx.x;
    int lane = tid & 31, wid = tid >> 5;
    int wm = wid & 3, wn = wid >> 2;

    float acc[2][WN / 8][4] = {};
    const int nch = (K / NSPLIT) / 32;

    auto load_stage = [&](int c, int s) {
        long kc = kc0 + (long)c * 32;
        u32 base = s2u(sm + s * STAGE);
        #pragma unroll
        for (int t = 0; t < 2; t++) {
            int idx = tid + t * 256;
            int r = idx >> 2, sg = idx & 3;
            long go = (long)(i0 + r) * lda + kc + sg * 8;
            u32 so = (u32)(r * STR + sg * 8) * 2;
            cpa16(base + so, Ah + go);
            cpa16(base + ASZ * 2 + so, Al + go);
        }
        #pragma unroll
        for (int t = 0; t < BN / 64; t++) {
            int idx = tid + t * 256;
            int r = idx >> 2, sg = idx & 3;
            long go = (long)(j0 + r) * ldb + kc + sg * 8;
            u32 so = (u32)(r * STR + sg * 8) * 2;
            cpa16(base + 4 * ASZ + so, Bh + go);
            cpa16(base + 4 * ASZ + 2 * BSZ + so, Bl + go);
        }
    };

    load_stage(0, 0);
    cpcommit();

    for (int c = 0; c < nch; c++) {
        if (c + 1 < nch) {
            load_stage(c + 1, (c + 1) & 1);
            cpcommit();
            cpwait1();
        } else {
            cpwait0();
        }
        __syncthreads();

        const bf* sAh = sm + (c & 1) * STAGE;
        const bf* sAl = sAh + ASZ;
        const bf* sBh = sAl + ASZ;
        const bf* sBl = sBh + BSZ;

        #pragma unroll
        for (int ks = 0; ks < 2; ks++) {
            u32 afh[2][4], afl[2][4];
            #pragma unroll
            for (int mt = 0; mt < 2; mt++) {
                int row = wm * 32 + mt * 16 + (lane & 15);
                int col = ks * 16 + (lane >> 4) * 8;
                ldsm_x4(afh[mt], s2u(&sAh[row * STR + col]));
                ldsm_x4(afl[mt], s2u(&sAl[row * STR + col]));
            }
            int sel = lane >> 3;
            #pragma unroll
            for (int np = 0; np < WN / 16; np++) {
                int brow = wn * WN + (np * 2 + (sel >> 1)) * 8 + (lane & 7);
                int bcol = ks * 16 + (sel & 1) * 8;
                u32 bh4[4], bl4[4];
                ldsm_x4(bh4, s2u(&sBh[brow * STR + bcol]));
                ldsm_x4(bl4, s2u(&sBl[brow * STR + bcol]));
                #pragma unroll
                for (int q = 0; q < 2; q++) {
                    int nt = np * 2 + q;
                    #pragma unroll
                    for (int mt = 0; mt < 2; mt++) {
                        mma16816(acc[mt][nt], afh[mt], bh4[2 * q], bh4[2 * q + 1]);
                        mma16816(acc[mt][nt], afh[mt], bl4[2 * q], bl4[2 * q + 1]);
                        mma16816(acc[mt][nt], afl[mt], bh4[2 * q], bh4[2 * q + 1]);
                    }
                }
            }
        }
        __syncthreads();
    }

    int grp = lane >> 2, qd = lane & 3;
    #pragma unroll
    for (int mt = 0; mt < 2; mt++) {
        #pragma unroll
        for (int nt = 0; nt < WN / 8; nt++) {
            int n = j0 + wn * WN + nt * 8 + qd * 2;
            float b0 = 0.f, b1 = 0.f;
            if (bias) { b0 = bias[n]; b1 = bias[n + 1]; }
            #pragma unroll
            for (int rh = 0; rh < 2; rh++) {
                int m = i0 + wm * 32 + mt * 16 + grp + rh * 8;
                float x = acc[mt][nt][rh * 2 + 0] + b0;
                float y = acc[mt][nt][rh * 2 + 1] + b1;
                if (GELU) {
                    x = 0.5f * x * (1.f + erff(x * 0.70710678118654752f));
                    y = 0.5f * y * (1.f + erff(y * 0.70710678118654752f));
                }
                long off = coff + (long)m * ldc + n;
                if (OMODE == 0) {
                    if (NSPLIT == 1) {
                        *(float2*)&C[off] = make_float2(x, y);
                    } else {
                        atomicAdd(&C[off], x);
                        atomicAdd(&C[off + 1], y);
                    }
                } else {
                    u32 hp, lp;
                    split2(x, y, hp, lp);
                    *(u32*)&Ch[off] = hp;
                    *(u32*)&Cl[off] = lp;
                }
            }
        }
    }
}

// ------------------------- flash attention (packed QKV, 2 streams) -------------------------
#define KVT 64
#define FSTR 72
#define FQSZ (128 * FSTR)
#define FKSZ (KVT * FSTR)
#define FSTG (4 * FKSZ)
#define FSMEM ((2 * FQSZ + 2 * FSTG) * 2)   // 110,592 B

__global__ void __launch_bounds__(256) flash_k(
    const bf* __restrict__ QKVh, const bf* __restrict__ QKVl,
    bf* __restrict__ Oh, bf* __restrict__ Ol,
    const unsigned* __restrict__ tptr)
{
    extern __shared__ __align__(16) bf fsm[];
    bf* sQh = fsm;
    bf* sQl = fsm + FQSZ;
    bf* stg = fsm + 2 * FQSZ;

    int q0 = blockIdx.x * 128;
    int y = blockIdx.y;
    int strm = y >> 5;
    int z = y & 31;
    int b = z / NHH, h = z - b * NHH;
    long qbase = (long)strm * NTOK * NQKV + (long)b * SS * NQKV + h * DD;
    long obase = (long)strm * TOKE + (long)b * SS * EE;

    int tid = threadIdx.x, lane = tid & 31, w = tid >> 5;
    int grp = lane >> 2, qd = lane & 3;
    int sel = lane >> 3;

    #pragma unroll
    for (int t = 0; t < 4; t++) {
        int idx = tid + t * 256;
        int r = idx >> 3, sg = idx & 7;
        long go = qbase + (long)(q0 + r) * NQKV + sg * 8;
        u32 so = (u32)(r * FSTR + sg * 8) * 2;
        cpa16(s2u(sQh) + so, QKVh + go);
        cpa16(s2u(sQl) + so, QKVl + go);
    }
    auto load_kv = [&](int c, int s) {
        bf* st = stg + s * FSTG;
        int kv0 = c * KVT;
        #pragma unroll
        for (int t = 0; t < 2; t++) {
            int idx = tid + t * 256;
            int r = idx >> 3, sg = idx & 7;
            u32 so = (u32)(r * FSTR + sg * 8) * 2;
            long gk = qbase + 512 + (long)(kv0 + r) * NQKV + sg * 8;
            cpa16(s2u(st) + so, QKVh + gk);
            cpa16(s2u(st + FKSZ) + so, QKVl + gk);
            long gv = qbase + 1024 + (long)(kv0 + r) * NQKV + sg * 8;
            cpa16(s2u(st + 2 * FKSZ) + so, QKVh + gv);
            cpa16(s2u(st + 3 * FKSZ) + so, QKVl + gv);
        }
    };
    load_kv(0, 0);
    cpcommit();

    float scl;
    {
        unsigned u = *tptr;
        float f = __uint_as_float(u);
        float temp = (f > 1e-6f && f < 1e6f) ? f : (float)(int)u;
        scl = 0.125f / temp;
    }

    float m0 = -1e30f, m1 = -1e30f, l0 = 0.f, l1 = 0.f;
    float acc_o[8][4] = {};

    const int NT = SS / KVT;
    for (int c = 0; c < NT; c++) {
        if (c + 1 < NT) { load_kv(c + 1, (c + 1) & 1); cpcommit(); cpwait1(); }
        else cpwait0();
        __syncthreads();
        bf* st = stg + (c & 1) * FSTG;
        bf* sKh = st;
        bf* sKl = st + FKSZ;
        bf* sVh = st + 2 * FKSZ;
        bf* sVl = st + 3 * FKSZ;

        float s_[8][4] = {};
        #pragma unroll
        for (int t = 0; t < 4; t++) {
            u32 ah4[4], al4[4];
            int arow = w * 16 + (lane & 15);
            int acol = t * 16 + (lane >> 4) * 8;
            ldsm_x4(ah4, s2u(&sQh[arow * FSTR + acol]));
            ldsm_x4(al4, s2u(&sQl[arow * FSTR + acol]));
            #pragma unroll
            for (int jp = 0; jp < 4; jp++) {
                int brow = (jp * 2 + (sel >> 1)) * 8 + (lane & 7);
                int bcol = t * 16 + (sel & 1) * 8;
                u32 bh4[4], bl4[4];
                ldsm_x4(bh4, s2u(&sKh[brow * FSTR + bcol]));
                ldsm_x4(bl4, s2u(&sKl[brow * FSTR + bcol]));
                #pragma unroll
                for (int q = 0; q < 2; q++) {
                    int j = jp * 2 + q;
                    mma16816(s_[j], ah4, bh4[2 * q], bh4[2 * q + 1]);
                    mma16816(s_[j], ah4, bl4[2 * q], bl4[2 * q + 1]);
                    mma16816(s_[j], al4, bh4[2 * q], bh4[2 * q + 1]);
                }
            }
        }
        float t0 = -1e30f, t1 = -1e30f;
        #pragma unroll
        for (int j = 0; j < 8; j++) {
            s_[j][0] *= scl; s_[j][1] *= scl; s_[j][2] *= scl; s_[j][3] *= scl;
            t0 = fmaxf(t0, fmaxf(s_[j][0], s_[j][1]));
            t1 = fmaxf(t1, fmaxf(s_[j][2], s_[j][3]));
        }
        t0 = fmaxf(t0, __shfl_xor_sync(0xffffffffu, t0, 1));
        t0 = fmaxf(t0, __shfl_xor_sync(0xffffffffu, t0, 2));
        t1 = fmaxf(t1, __shfl_xor_sync(0xffffffffu, t1, 1));
        t1 = fmaxf(t1, __shfl_xor_sync(0xffffffffu, t1, 2));
        float nm0 = fmaxf(m0, t0), nm1 = fmaxf(m1, t1);
        float corr0 = __expf(m0 - nm0), corr1 = __expf(m1 - nm1);
        m0 = nm0; m1 = nm1;
        float sum0 = 0.f, sum1 = 0.f;
        #pragma unroll
        for (int j = 0; j < 8; j++) {
            s_[j][0] = __expf(s_[j][0] - m0);
            s_[j][1] = __expf(s_[j][1] - m0);
            s_[j][2] = __expf(s_[j][2] - m1);
            s_[j][3] = __expf(s_[j][3] - m1);
            sum0 += s_[j][0] + s_[j][1];
            sum1 += s_[j][2] + s_[j][3];
        }
        sum0 += __shfl_xor_sync(0xffffffffu, sum0, 1);
        sum0 += __shfl_xor_sync(0xffffffffu, sum0, 2);
        sum1 += __shfl_xor_sync(0xffffffffu, sum1, 1);
        sum1 += __shfl_xor_sync(0xffffffffu, sum1, 2);
        l0 = l0 * corr0 + sum0;
        l1 = l1 * corr1 + sum1;
        #pragma unroll
        for (int n = 0; n < 8; n++) {
            acc_o[n][0] *= corr0; acc_o[n][1] *= corr0;
            acc_o[n][2] *= corr1; acc_o[n][3] *= corr1;
        }
        #pragma unroll
        for (int t = 0; t < 4; t++) {
            u32 pah[4], pal[4];
            split2(s_[2 * t][0],     s_[2 * t][1],     pah[0], pal[0]);
            split2(s_[2 * t][2],     s_[2 * t][3],     pah[1], pal[1]);
            split2(s_[2 * t + 1][0], s_[2 * t + 1][1], pah[2], pal[2]);
            split2(s_[2 * t + 1][2], s_[2 * t + 1][3], pah[3], pal[3]);
            int vrow = t * 16 + (lane & 15);
            #pragma unroll
            for (int np = 0; np < 4; np++) {
                int vcol = (np * 2 + (lane >> 4)) * 8;
                u32 bh4[4], bl4[4];
                ldsm_x4t(bh4, s2u(&sVh[vrow * FSTR + vcol]));
                ldsm_x4t(bl4, s2u(&sVl[vrow * FSTR + vcol]));
                #pragma unroll
                for (int q = 0; q < 2; q++) {
                    int n = np * 2 + q;
                    mma16816(acc_o[n], pah, bh4[2 * q], bh4[2 * q + 1]);
                    mma16816(acc_o[n], pah, bl4[2 * q], bl4[2 * q + 1]);
                    mma16816(acc_o[n], pal, bh4[2 * q], bh4[2 * q + 1]);
                }
            }
        }
        __syncthreads();
    }

    float inv0 = 1.f / l0, inv1 = 1.f / l1;
    int r0 = q0 + w * 16 + grp;
    #pragma unroll
    for (int n = 0; n < 8; n++) {
        int col = h * DD + n * 8 + qd * 2;
        {
            long off = obase + (long)r0 * EE + col;
            u32 hp, lp;
            split2(acc_o[n][0] * inv0, acc_o[n][1] * inv0, hp, lp);
            *(u32*)&Oh[off] = hp;
            *(u32*)&Ol[off] = lp;
        }
        {
            long off = obase + (long)(r0 + 8) * EE + col;
            u32 hp, lp;
            split2(acc_o[n][2] * inv1, acc_o[n][3] * inv1, hp, lp);
            *(u32*)&Oh[off] = hp;
            *(u32*)&Ol[off] = lp;
        }
    }
}

// ------------------------- ONE-launch preprocessing -------------------------
__global__ void prep_k(const float* __restrict__ qw, const float* __restrict__ kw,
                       const float* __restrict__ vw, const float* __restrict__ ow,
                       const float* __restrict__ w1, const float* __restrict__ w2,
                       const float* __restrict__ qb, const float* __restrict__ kb,
                       const float* __restrict__ vb,
                       const float* __restrict__ in0, const float* __restrict__ in1)
{
    int t = blockIdx.x;
    int tx = threadIdx.x, ty = threadIdx.y;
    int ltid = ty * 32 + tx;

    if (t >= 8200) {
        int idx = t - 8200;
        int strm = idx >> 11;
        long i = (long)(idx & 2047) * 1024 + ltid * 4;
        const float* x = strm ? in1 : in0;
        float4 v = *(const float4*)(x + i);
        u32 hp[2], lp[2];
        split2(v.x, v.y, hp[0], lp[0]);
        split2(v.z, v.w, hp[1], lp[1]);
        long o = (long)strm * TOKE + i;
        *(uint2*)(g_xh + o) = make_uint2(hp[0], hp[1]);
        *(uint2*)(g_xl + o) = make_uint2(lp[0], lp[1]);
        return;
    }
    if (t >= 8192) {
        int blk = t - 8192;
        int i = blk >> 1;
        int tt = (blk & 1) * 256 + ltid;
        g_qkvb[i * NQKV + tt]        = qb[i * EE + tt];
        g_qkvb[i * NQKV + 512 + tt]  = kb[i * EE + tt];
        g_qkvb[i * NQKV + 1024 + tt] = vb[i * EE + tt];
        return;
    }

    __shared__ float sm[32][33];
    const float* src;
    bf *dh, *dl;
    int lds, ldd, ry, cx;

    if (t < 4096) {
        int g = t >> 10, rem = t & 1023;
        int b = rem >> 8, tt = rem & 255;
        ry = tt >> 4; cx = tt & 15;
        lds = 512; ldd = 512;
        const float* s4 = (g == 0) ? qw : (g == 1) ? kw : (g == 2) ? vw : ow;
        src = s4 + (long)b * WEE_B;
        if (g < 3) {
            dh = g_wqkvh + (long)b * WQKV_B + (long)g * 512 * EE;
            dl = g_wqkvl + (long)b * WQKV_B + (long)g * 512 * EE;
        } else {
            dh = g_owth + (long)b * WEE_B;
            dl = g_owtl + (long)b * WEE_B;
        }
    } else if (t < 6144) {
        int t2 = t - 4096;
        int b = t2 >> 10, tt = t2 & 1023;
        ry = tt >> 6; cx = tt & 63;
        lds = 2048; ldd = 512;
        src = w1 + (long)b * WFF_B;
        dh = g_w1th + (long)b * WFF_B;
        dl = g_w1tl + (long)b * WFF_B;
    } else {
        int t3 = t - 6144;
        int b = t3 >> 10, tt = t3 & 1023;
        ry = tt >> 4; cx = tt & 15;
        lds = 512; ldd = 2048;
        src = w2 + (long)b * WFF_B;
        dh = g_w2th + (long)b * WFF_B;
        dl = g_w2tl + (long)b * WFF_B;
    }

    int r0 = ry * 32, c0 = cx * 32;
    #pragma unroll
    for (int i = 0; i < 4; i++)
        sm[ty + 8 * i][tx] = src[(long)(r0 + ty + 8 * i) * lds + c0 + tx];
    __syncthreads();
    #pragma unroll
    for (int i = 0; i < 4; i++) {
        int n = c0 + ty + 8 * i, k = r0 + tx;
        float v = sm[tx][ty + 8 * i];
        bf hv = __float2bfloat16(v);
        bf lv = __float2bfloat16(v - __bfloat162float(hv));
        dh[(long)n * ldd + k] = hv;
        dl[(long)n * ldd + k] = lv;
    }
}

// ------------------------- batched residual + layernorm (+ optional split out) -----
__global__ void ln2_k(const float* __restrict__ x0, const float* __restrict__ x1,
                      const float* __restrict__ res,
                      const float* __restrict__ g0, const float* __restrict__ b0_,
                      const float* __restrict__ g1, const float* __restrict__ b1_,
                      float* __restrict__ out,
                      bf* __restrict__ oh = nullptr,
                      bf* __restrict__ ol = nullptr)
{
    long row = blockIdx.x;
    int strm = row >= NTOK;
    long r = row - (long)strm * NTOK;
    const float* x = (strm ? x1 : x0) + r * EE;
    const float* gamma = strm ? g1 : g0;
    const float* beta  = strm ? b1_ : b0_;
    int t = threadIdx.x;
    float4 v = ((const float4*)x)[t];
    if (res) {
        float4 rr = ((const float4*)(res + row * EE))[t];
        v.x += rr.x; v.y += rr.y; v.z += rr.z; v.w += rr.w;
    }
    float s = v.x + v.y + v.z + v.w;
    float q = v.x * v.x + v.y * v.y + v.z * v.z + v.w * v.w;
    #pragma unroll
    for (int o = 16; o; o >>= 1) {
        s += __shfl_xor_sync(0xffffffffu, s, o);
        q += __shfl_xor_sync(0xffffffffu, q, o);
    }
    __shared__ float shS[4], shQ[4];
    int w = t >> 5;
    if ((t & 31) == 0) { shS[w] = s; shQ[w] = q; }
    __syncthreads();
    s = shS[0] + shS[1] + shS[2] + shS[3];
    q = shQ[0] + shQ[1] + shQ[2] + shQ[3];
    float mean = s * (1.f / EE);
    float var = q * (1.f / EE) - mean * mean;
    float rstd = rsqrtf(var + 1e-5f);
    float4 g = ((const float4*)gamma)[t];
    float4 b = ((const float4*)beta)[t];
    float4 o;
    o.x = (v.x - mean) * rstd * g.x + b.x;
    o.y = (v.y - mean) * rstd * g.y + b.y;
    o.z = (v.z - mean) * rstd * g.z + b.z;
    o.w = (v.w - mean) * rstd * g.w + b.w;
    ((float4*)(out + row * EE))[t] = o;
    if (oh) {
        u32 hp[2], lp[2];
        split2(o.x, o.y, hp[0], lp[0]);
        split2(o.z, o.w, hp[1], lp[1]);
        *(uint2*)(oh + row * EE + t * 4) = make_uint2(hp[0], hp[1]);
        *(uint2*)(ol + row * EE + t * 4) = make_uint2(lp[0], lp[1]);
    }
}

// ------------------------- fused gate + mix + norm2 (gamma shared) -------------------------
__global__ void gate_mix_ln_k(const float* __restrict__ x, const float* __restrict__ cr,
                              const float* __restrict__ gw, const float* __restrict__ gb,
                              const float* __restrict__ gamma, const float* __restrict__ beta,
                              float* __restrict__ out,
                              bf* __restrict__ oh, bf* __restrict__ ol)
{
    long row = blockIdx.x;
    int t = threadIdx.x;
    float4 xv = ((const float4*)(x + row * EE))[t];
    float4 cv = ((const float4*)(cr + row * EE))[t];
    int k0 = t * 4;
    float l0 = 0.f, l1 = 0.f;
    float xs[4] = {xv.x, xv.y, xv.z, xv.w};
    float cs[4] = {cv.x, cv.y, cv.z, cv.w};
    #pragma unroll
    for (int e = 0; e < 4; e++) {
        int k = k0 + e;
        l0 += xs[e] * gw[k * 2 + 0] + cs[e] * gw[(EE + k) * 2 + 0];
        l1 += xs[e] * gw[k * 2 + 1] + cs[e] * gw[(EE + k) * 2 + 1];
    }
    #pragma unroll
    for (int o = 16; o; o >>= 1) {
        l0 += __shfl_xor_sync(0xffffffffu, l0, o);
        l1 += __shfl_xor_sync(0xffffffffu, l1, o);
    }
    __shared__ float sh0[4], sh1[4];
    int w = t >> 5;
    if ((t & 31) == 0) { sh0[w] = l0; sh1[w] = l1; }
    __syncthreads();
    l0 = sh0[0] + sh0[1] + sh0[2] + sh0[3] + gb[0];
    l1 = sh1[0] + sh1[1] + sh1[2] + sh1[3] + gb[1];
    float mx = fmaxf(l0, l1);
    float e0 = __expf(l0 - mx), e1 = __expf(l1 - mx);
    float gg0 = e0 / (e0 + e1), gg1 = e1 / (e0 + e1);
    float4 v;
    v.x = xv.x * gg0 + cv.x * gg1;
    v.y = xv.y * gg0 + cv.y * gg1;
    v.z = xv.z * gg0 + cv.z * gg1;
    v.w = xv.w * gg0 + cv.w * gg1;

    float s = v.x + v.y + v.z + v.w;
    float q = v.x * v.x + v.y * v.y + v.z * v.z + v.w * v.w;
    #pragma unroll
    for (int o = 16; o; o >>= 1) {
        s += __shfl_xor_sync(0xffffffffu, s, o);
        q += __shfl_xor_sync(0xffffffffu, q, o);
    }
    __syncthreads();
    if ((t & 31) == 0) { sh0[w] = s; sh1[w] = q; }
    __syncthreads();
    s = sh0[0] + sh0[1] + sh0[2] + sh0[3];
    q = sh1[0] + sh1[1] + sh1[2] + sh1[3];
    float mean = s * (1.f / EE);
    float var = q * (1.f / EE) - mean * mean;
    float rstd = rsqrtf(var + 1e-5f);
    float4 g = ((const float4*)gamma)[t];
    float4 b = ((const float4*)beta)[t];
    float4 o;
    o.x = (v.x - mean) * rstd * g.x + b.x;
    o.y = (v.y - mean) * rstd * g.y + b.y;
    o.z = (v.z - mean) * rstd * g.z + b.z;
    o.w = (v.w - mean) * rstd * g.w + b.w;
    ((float4*)(out + row * EE))[t] = o;
    u32 hp[2], lp[2];
    split2(o.x, o.y, hp[0], lp[0]);
    split2(o.z, o.w, hp[1], lp[1]);
    *(uint2*)(oh + row * EE + t * 4) = make_uint2(hp[0], hp[1]);
    *(uint2*)(ol + row * EE + t * 4) = make_uint2(lp[0], lp[1]);
}

// ------------------------- host orchestration -------------------------
static float* sym(const void* s) { void* p = nullptr; cudaGetSymbolAddress(&p, s); return (float*)p; }
static bf* symb(const void* s)   { void* p = nullptr; cudaGetSymbolAddress(&p, s); return (bf*)p; }

#define SMEM64 ((2 * 128 * 40 + 2 * 128 * 40) * 2 * 2)   // 81920 B
#define JBIG (1 << 30)

// split-K=2 fp32-output GEMM (atomicAdd into zeroed C; 2 addends -> deterministic)
static void bg_f32(const bf* ah, const bf* al, const bf* bh, const bf* bl, long aB, long bB,
                   const float* bias, long biasB, float* C, long cB, int M, int N, int K, int ldc) {
    dim3 grid(N / 128, M / 128, 4);
    gemm_mma<64, 0, false, 2><<<grid, 256, SMEM64>>>(ah, al, bh, bl, bias, C, nullptr, nullptr,
        K, K, K, ldc, aB, bB, cB, biasB, JBIG, 0, 0);
}
static void bg_sp(const bf* ah, const bf* al, const bf* bh, const bf* bl, long aB, long bB,
                  const float* bias, long biasB, bf* Ch, bf* Cl, long cB,
                  int M, int N, int K, int ldc, bool gelu,
                  int jsplit = JBIG, long aOff2 = 0, long aB2 = 0) {
    dim3 grid(N / 128, M / 128, 2);
    if (gelu)
        gemm_mma<64, 2, true, 1><<<grid, 256, SMEM64>>>(ah, al, bh, bl, bias, nullptr, Ch, Cl,
            K, K, K, ldc, aB, bB, cB, biasB, jsplit, aOff2, aB2);
    else
        gemm_mma<64, 2, false, 1><<<grid, 256, SMEM64>>>(ah, al, bh, bl, bias, nullptr, Ch, Cl,
            K, K, K, ldc, aB, bB, cB, biasB, jsplit, aOff2, aB2);
}

extern "C" void kernel_launch(void* const* d_in, const int* in_sizes, int n_in,
                              void* d_out, int out_size)
{
    const float* body_feats = (const float*)d_in[0];
    const float* limb_feats = (const float*)d_in[1];
    const float* attn_qw = (const float*)d_in[2];
    const float* attn_qb = (const float*)d_in[3];
    const float* attn_kw = (const float*)d_in[4];
    const float* attn_kb = (const float*)d_in[5];
    const float* attn_vw = (const float*)d_in[6];
    const float* attn_vb = (const float*)d_in[7];
    const float* attn_ow = (const float*)d_in[8];
    const float* attn_ob = (const float*)d_in[9];
    const float* ffn_w1 = (const float*)d_in[10];
    const float* ffn_b1 = (const float*)d_in[11];
    const float* ffn_w2 = (const float*)d_in[12];
    const float* ffn_b2 = (const float*)d_in[13];
    const float* nsc = (const float*)d_in[14];
    const float* nbi = (const float*)d_in[15];
    const float* gw = (const float*)d_in[16];
    const float* gb = (const float*)d_in[17];
    const unsigned* temp = (const unsigned*)d_in[18];

    cudaFuncSetAttribute(gemm_mma<64, 0, false, 2>, cudaFuncAttributeMaxDynamicSharedMemorySize, SMEM64);
    cudaFuncSetAttribute(gemm_mma<64, 2, false, 1>, cudaFuncAttributeMaxDynamicSharedMemorySize, SMEM64);
    cudaFuncSetAttribute(gemm_mma<64, 2, true, 1>,  cudaFuncAttributeMaxDynamicSharedMemorySize, SMEM64);
    cudaFuncSetAttribute(flash_k, cudaFuncAttributeMaxDynamicSharedMemorySize, FSMEM);

    float* out = (float*)d_out;

    float* tmp  = sym(g_tmp);
    float* bl   = sym(g_bl);
    float* cross = sym(g_cross);
    float* ffn  = sym(g_ffn);
    bf *xh = symb(g_xh), *xl = symb(g_xl);
    bf *s1h = symb(g_s1h), *s1l = symb(g_s1l);
    bf *qkvh = symb(g_qkvh), *qkvl = symb(g_qkvl);
    bf *atth = symb(g_atth), *attl = symb(g_attl);
    bf *hidh = symb(g_hidh), *hidl = symb(g_hidl);
    bf *wqh = symb(g_wqkvh), *wql = symb(g_wqkvl);
    bf *owh = symb(g_owth), *owl = symb(g_owtl);
    bf *w1h = symb(g_w1th), *w1l = symb(g_w1tl);
    bf *w2h = symb(g_w2th), *w2l = symb(g_w2tl);
    const float* qkvb = sym(g_qkvb);

    // ---- zero split-K accumulation buffers (graph-capturable async memsets) ----
    cudaMemsetAsync(tmp,   0, (size_t)2 * NTOK * EE * sizeof(float));
    cudaMemsetAsync(cross, 0, (size_t)2 * NTOK * EE * sizeof(float));
    cudaMemsetAsync(ffn,   0, (size_t)2 * NTOK * EE * sizeof(float));

    // ---- preprocessing (ONE launch) ----
    prep_k<<<12296, dim3(32, 8)>>>(attn_qw, attn_kw, attn_vw, attn_ow, ffn_w1, ffn_w2,
                                   attn_qb, attn_kb, attn_vb, body_feats, limb_feats);

    // ---- self attention (batched over body/limb) ----
    bg_sp(xh, xl, wqh, wql, TOKE, WQKV_B, qkvb, NQKV,
          qkvh, qkvl, QKV_B, NTOK, NQKV, EE, NQKV, false);
    flash_k<<<dim3(SS / 128, 2 * NB), 256, FSMEM>>>(qkvh, qkvl, atth, attl, temp);
    bg_f32(atth, attl, owh, owl, TOKE, WEE_B, attn_ob, EE, tmp, TOKE, NTOK, EE, EE, EE);

    // norm1 (batched): body gamma 0, limb gamma 3
    ln2_k<<<2 * NTOK, 128>>>(body_feats, limb_feats, tmp,
                             nsc + 0 * EE, nbi + 0 * EE, nsc + 3 * EE, nbi + 3 * EE,
                             bl, s1h, s1l);

    // ---- cross attention: ONE fused QKV launch ----
    bg_sp(s1h, s1l, wqh + 2 * WQKV_B, wql + 2 * WQKV_B, TOKE, WQKV_B,
          qkvb + 2 * NQKV, NQKV, qkvh, qkvl, QKV_B, NTOK, NQKV, EE, NQKV, false,
          /*jsplit=*/512, /*aOff2=*/TOKE, /*aB2=*/-TOKE);
    flash_k<<<dim3(SS / 128, 2 * NB), 256, FSMEM>>>(qkvh, qkvl, atth, attl, temp);
    bg_f32(atth, attl, owh + 2 * WEE_B, owl + 2 * WEE_B, TOKE, WEE_B,
           attn_ob + 2 * EE, EE, cross, TOKE, NTOK, EE, EE, EE);

    // ---- fused gate + mix + norm2 (gamma 1 on BOTH streams — faithful) ----
    gate_mix_ln_k<<<2 * NTOK, 128>>>(bl, cross, gw, gb,
                                     nsc + 1 * EE, nbi + 1 * EE, bl, s1h, s1l);

    // ---- FFN (batched) ----
    bg_sp(s1h, s1l, w1h, w1l, TOKE, WFF_B, ffn_b1, 4 * EE,
          hidh, hidl, HID_B, NTOK, 4 * EE, EE, 4 * EE, true);
    bg_f32(hidh, hidl, w2h, w2l, HID_B, WFF_B, ffn_b2, EE, ffn, TOKE, NTOK, EE, 4 * EE, EE);

    // final norms (batched): body gamma 2, limb gamma 5 -> out
    ln2_k<<<2 * NTOK, 128>>>(bl, bl + TOKE, ffn,
                             nsc + 2 * EE, nbi + 2 * EE, nsc + 5 * EE, nbi + 5 * EE,
                             out, nullptr, nullptr);
}

// round 17
// speedup vs baseline: 1.1440x; 1.0483x over previous
#include <cuda_runtime.h>
#include <cuda_bf16.h>
#include <math.h>

typedef unsigned int u32;
typedef unsigned long long u64;
typedef __nv_bfloat16 bf;

#define BB 4
#define SS 1024
#define EE 512
#define NHH 8
#define DD 64
#define NTOK (BB*SS)          // 4096
#define TOKE ((long)NTOK*EE)  // 2,097,152
#define NB (BB*NHH)           // 32
#define NQKV 1536

#define WEE_B ((long)EE*EE)
#define WQKV_B ((long)NQKV*EE)
#define WFF_B ((long)EE*4*EE)
#define QKV_B ((long)NTOK*NQKV)
#define HID_B ((long)NTOK*4*EE)

// ------------------------- fp32 scratch ([2] = body, limb) -------------------------
__device__ float g_tmp[2*NTOK*EE];
__device__ float g_bl[2*NTOK*EE];
__device__ float g_cross[2*NTOK*EE];
__device__ float g_ffn[2*NTOK*EE];
__device__ float g_qkvb[4*NQKV];

// ------------------------- bf16 split scratch (16B aligned) -------------------------
__device__ __align__(16) bf g_xh[2*NTOK*EE], g_xl[2*NTOK*EE];
__device__ __align__(16) bf g_s1h[2*NTOK*EE], g_s1l[2*NTOK*EE];
__device__ __align__(16) bf g_qkvh[(long)2*NTOK*NQKV], g_qkvl[(long)2*NTOK*NQKV];
__device__ __align__(16) bf g_atth[2*NTOK*EE], g_attl[2*NTOK*EE];
__device__ __align__(16) bf g_hidh[(long)2*NTOK*4*EE], g_hidl[(long)2*NTOK*4*EE];
__device__ __align__(16) bf g_wqkvh[(long)4*NQKV*EE], g_wqkvl[(long)4*NQKV*EE];
__device__ __align__(16) bf g_owth[4*EE*EE], g_owtl[4*EE*EE];
__device__ __align__(16) bf g_w1th[(long)2*EE*4*EE], g_w1tl[(long)2*EE*4*EE];
__device__ __align__(16) bf g_w2th[(long)2*EE*4*EE], g_w2tl[(long)2*EE*4*EE];

// ------------------------- asm helpers -------------------------
__device__ __forceinline__ u32 s2u(const void* p) {
    u32 a;
    asm("{ .reg .u64 t; cvta.to.shared.u64 t, %1; cvt.u32.u64 %0, t; }" : "=r"(a) : "l"(p));
    return a;
}
__device__ __forceinline__ void cpa16(u32 saddr, const void* g) {
    asm volatile("cp.async.cg.shared.global [%0], [%1], 16;" :: "r"(saddr), "l"(g));
}
__device__ __forceinline__ void cpcommit() { asm volatile("cp.async.commit_group;"); }
__device__ __forceinline__ void cpwait1()  { asm volatile("cp.async.wait_group 1;"); }
__device__ __forceinline__ void cpwait0()  { asm volatile("cp.async.wait_group 0;"); }

__device__ __forceinline__ void ldsm_x4(u32 r[4], u32 addr) {
    asm volatile("ldmatrix.sync.aligned.m8n8.x4.shared.b16 {%0,%1,%2,%3}, [%4];"
                 : "=r"(r[0]), "=r"(r[1]), "=r"(r[2]), "=r"(r[3]) : "r"(addr));
}
__device__ __forceinline__ void ldsm_x4t(u32 r[4], u32 addr) {
    asm volatile("ldmatrix.sync.aligned.m8n8.x4.trans.shared.b16 {%0,%1,%2,%3}, [%4];"
                 : "=r"(r[0]), "=r"(r[1]), "=r"(r[2]), "=r"(r[3]) : "r"(addr));
}
__device__ __forceinline__ void mma16816(float c[4], const u32 a[4], const u32 b0, const u32 b1) {
    asm volatile(
        "mma.sync.aligned.m16n8k16.row.col.f32.bf16.bf16.f32 "
        "{%0,%1,%2,%3}, {%4,%5,%6,%7}, {%8,%9}, {%0,%1,%2,%3};"
        : "+f"(c[0]), "+f"(c[1]), "+f"(c[2]), "+f"(c[3])
        : "r"(a[0]), "r"(a[1]), "r"(a[2]), "r"(a[3]), "r"(b0), "r"(b1));
}
__device__ __forceinline__ void split2(float x, float y, u32& hp, u32& lp) {
    bf hx = __float2bfloat16(x), hy = __float2bfloat16(y);
    bf lx = __float2bfloat16(x - __bfloat162float(hx));
    bf ly = __float2bfloat16(y - __bfloat162float(hy));
    hp = (u32)__bfloat16_as_ushort(hx) | ((u32)__bfloat16_as_ushort(hy) << 16);
    lp = (u32)__bfloat16_as_ushort(lx) | ((u32)__bfloat16_as_ushort(ly) << 16);
}

// ------------------------- bf16-split tensor-core GEMM, cp.async pipelined -----
// 128x128 tile (WN=64), 8 warps 4m x 2n, dual-sync 2-stage pipeline (R13 proven).
// __launch_bounds__(256,2) pins the 2-CTA/SM residency (regs <= 128).
// Per batch z: C[i,j] = act(sum_l A[i,l]*B[j,l] + bias[j]).
// A-offset rule: column tiles with j0 < jsplit use z*aB; else aOff2 + z*aB2.
// OMODE: 0 fp32; 2 bf16 hi/lo.
template<int WN, int OMODE, bool GELU>
__global__ void __launch_bounds__(256, 2) gemm_mma(
    const bf* __restrict__ Ah, const bf* __restrict__ Al,
    const bf* __restrict__ Bh, const bf* __restrict__ Bl,
    const float* __restrict__ bias, float* __restrict__ C,
    bf* __restrict__ Ch, bf* __restrict__ Cl,
    int K, int lda, int ldb, int ldc,
    long aB, long bB, long cB, long biasB,
    int jsplit, long aOff2, long aB2)
{
    constexpr int BN = 2 * WN;
    constexpr int STR = 40;
    constexpr int ASZ = 128 * STR;
    constexpr int BSZ = BN * STR;
    constexpr int STAGE = 2 * ASZ + 2 * BSZ;

    extern __shared__ __align__(16) bf sm[];

    int z = blockIdx.z;
    int j0 = blockIdx.x * BN;
    long aoff = (j0 < jsplit) ? z * aB : aOff2 + z * aB2;
    Ah += aoff;  Al += aoff;
    Bh += z * bB;  Bl += z * bB;
    if (bias) bias += z * biasB;
    long coff = z * cB;

    int i0 = blockIdx.y * 128;
    int tid = threadIdx.x;
    int lane = tid & 31, wid = tid >> 5;
    int wm = wid & 3, wn = wid >> 2;

    float acc[2][WN / 8][4] = {};
    const int nch = K / 32;

    auto load_stage = [&](int c, int s) {
        long kc = (long)c * 32;
        u32 base = s2u(sm + s * STAGE);
        #pragma unroll
        for (int t = 0; t < 2; t++) {
            int idx = tid + t * 256;
            int r = idx >> 2, sg = idx & 3;
            long go = (long)(i0 + r) * lda + kc + sg * 8;
            u32 so = (u32)(r * STR + sg * 8) * 2;
            cpa16(base + so, Ah + go);
            cpa16(base + ASZ * 2 + so, Al + go);
        }
        #pragma unroll
        for (int t = 0; t < BN / 64; t++) {
            int idx = tid + t * 256;
            int r = idx >> 2, sg = idx & 3;
            long go = (long)(j0 + r) * ldb + kc + sg * 8;
            u32 so = (u32)(r * STR + sg * 8) * 2;
            cpa16(base + 4 * ASZ + so, Bh + go);
            cpa16(base + 4 * ASZ + 2 * BSZ + so, Bl + go);
        }
    };

    load_stage(0, 0);
    cpcommit();

    for (int c = 0; c < nch; c++) {
        if (c + 1 < nch) {
            load_stage(c + 1, (c + 1) & 1);
            cpcommit();
            cpwait1();
        } else {
            cpwait0();
        }
        __syncthreads();

        const bf* sAh = sm + (c & 1) * STAGE;
        const bf* sAl = sAh + ASZ;
        const bf* sBh = sAl + ASZ;
        const bf* sBl = sBh + BSZ;

        #pragma unroll
        for (int ks = 0; ks < 2; ks++) {
            u32 afh[2][4], afl[2][4];
            #pragma unroll
            for (int mt = 0; mt < 2; mt++) {
                int row = wm * 32 + mt * 16 + (lane & 15);
                int col = ks * 16 + (lane >> 4) * 8;
                ldsm_x4(afh[mt], s2u(&sAh[row * STR + col]));
                ldsm_x4(afl[mt], s2u(&sAl[row * STR + col]));
            }
            int sel = lane >> 3;
            #pragma unroll
            for (int np = 0; np < WN / 16; np++) {
                int brow = wn * WN + (np * 2 + (sel >> 1)) * 8 + (lane & 7);
                int bcol = ks * 16 + (sel & 1) * 8;
                u32 bh4[4], bl4[4];
                ldsm_x4(bh4, s2u(&sBh[brow * STR + bcol]));
                ldsm_x4(bl4, s2u(&sBl[brow * STR + bcol]));
                #pragma unroll
                for (int q = 0; q < 2; q++) {
                    int nt = np * 2 + q;
                    #pragma unroll
                    for (int mt = 0; mt < 2; mt++) {
                        mma16816(acc[mt][nt], afh[mt], bh4[2 * q], bh4[2 * q + 1]);
                        mma16816(acc[mt][nt], afh[mt], bl4[2 * q], bl4[2 * q + 1]);
                        mma16816(acc[mt][nt], afl[mt], bh4[2 * q], bh4[2 * q + 1]);
                    }
                }
            }
        }
        __syncthreads();
    }

    int grp = lane >> 2, qd = lane & 3;
    #pragma unroll
    for (int mt = 0; mt < 2; mt++) {
        #pragma unroll
        for (int nt = 0; nt < WN / 8; nt++) {
            int n = j0 + wn * WN + nt * 8 + qd * 2;
            float b0 = 0.f, b1 = 0.f;
            if (bias) { b0 = bias[n]; b1 = bias[n + 1]; }
            #pragma unroll
            for (int rh = 0; rh < 2; rh++) {
                int m = i0 + wm * 32 + mt * 16 + grp + rh * 8;
                float x = acc[mt][nt][rh * 2 + 0] + b0;
                float y = acc[mt][nt][rh * 2 + 1] + b1;
                if (GELU) {
                    x = 0.5f * x * (1.f + erff(x * 0.70710678118654752f));
                    y = 0.5f * y * (1.f + erff(y * 0.70710678118654752f));
                }
                long off = coff + (long)m * ldc + n;
                if (OMODE == 0) {
                    *(float2*)&C[off] = make_float2(x, y);
                } else {
                    u32 hp, lp;
                    split2(x, y, hp, lp);
                    *(u32*)&Ch[off] = hp;
                    *(u32*)&Cl[off] = lp;
                }
            }
        }
    }
}

// ------------------------- flash attention (packed QKV, 2 streams) -------------------------
// smem 110,592 B: 2 CTAs/SM fit (221KB <= 228KB). __launch_bounds__(256,2)
// caps regs at 128 so registers don't block the second CTA.
#define KVT 64
#define FSTR 72
#define FQSZ (128 * FSTR)
#define FKSZ (KVT * FSTR)
#define FSTG (4 * FKSZ)
#define FSMEM ((2 * FQSZ + 2 * FSTG) * 2)   // 110,592 B

__global__ void __launch_bounds__(256, 2) flash_k(
    const bf* __restrict__ QKVh, const bf* __restrict__ QKVl,
    bf* __restrict__ Oh, bf* __restrict__ Ol,
    const unsigned* __restrict__ tptr)
{
    extern __shared__ __align__(16) bf fsm[];
    bf* sQh = fsm;
    bf* sQl = fsm + FQSZ;
    bf* stg = fsm + 2 * FQSZ;

    int q0 = blockIdx.x * 128;
    int y = blockIdx.y;
    int strm = y >> 5;
    int z = y & 31;
    int b = z / NHH, h = z - b * NHH;
    long qbase = (long)strm * NTOK * NQKV + (long)b * SS * NQKV + h * DD;
    long obase = (long)strm * TOKE + (long)b * SS * EE;

    int tid = threadIdx.x, lane = tid & 31, w = tid >> 5;
    int grp = lane >> 2, qd = lane & 3;
    int sel = lane >> 3;

    #pragma unroll
    for (int t = 0; t < 4; t++) {
        int idx = tid + t * 256;
        int r = idx >> 3, sg = idx & 7;
        long go = qbase + (long)(q0 + r) * NQKV + sg * 8;
        u32 so = (u32)(r * FSTR + sg * 8) * 2;
        cpa16(s2u(sQh) + so, QKVh + go);
        cpa16(s2u(sQl) + so, QKVl + go);
    }
    auto load_kv = [&](int c, int s) {
        bf* st = stg + s * FSTG;
        int kv0 = c * KVT;
        #pragma unroll
        for (int t = 0; t < 2; t++) {
            int idx = tid + t * 256;
            int r = idx >> 3, sg = idx & 7;
            u32 so = (u32)(r * FSTR + sg * 8) * 2;
            long gk = qbase + 512 + (long)(kv0 + r) * NQKV + sg * 8;
            cpa16(s2u(st) + so, QKVh + gk);
            cpa16(s2u(st + FKSZ) + so, QKVl + gk);
            long gv = qbase + 1024 + (long)(kv0 + r) * NQKV + sg * 8;
            cpa16(s2u(st + 2 * FKSZ) + so, QKVh + gv);
            cpa16(s2u(st + 3 * FKSZ) + so, QKVl + gv);
        }
    };
    load_kv(0, 0);
    cpcommit();

    float scl;
    {
        unsigned u = *tptr;
        float f = __uint_as_float(u);
        float temp = (f > 1e-6f && f < 1e6f) ? f : (float)(int)u;
        scl = 0.125f / temp;
    }

    float m0 = -1e30f, m1 = -1e30f, l0 = 0.f, l1 = 0.f;
    float acc_o[8][4] = {};

    const int NT = SS / KVT;
    for (int c = 0; c < NT; c++) {
        if (c + 1 < NT) { load_kv(c + 1, (c + 1) & 1); cpcommit(); cpwait1(); }
        else cpwait0();
        __syncthreads();
        bf* st = stg + (c & 1) * FSTG;
        bf* sKh = st;
        bf* sKl = st + FKSZ;
        bf* sVh = st + 2 * FKSZ;
        bf* sVl = st + 3 * FKSZ;

        float s_[8][4] = {};
        #pragma unroll
        for (int t = 0; t < 4; t++) {
            u32 ah4[4], al4[4];
            int arow = w * 16 + (lane & 15);
            int acol = t * 16 + (lane >> 4) * 8;
            ldsm_x4(ah4, s2u(&sQh[arow * FSTR + acol]));
            ldsm_x4(al4, s2u(&sQl[arow * FSTR + acol]));
            #pragma unroll
            for (int jp = 0; jp < 4; jp++) {
                int brow = (jp * 2 + (sel >> 1)) * 8 + (lane & 7);
                int bcol = t * 16 + (sel & 1) * 8;
                u32 bh4[4], bl4[4];
                ldsm_x4(bh4, s2u(&sKh[brow * FSTR + bcol]));
                ldsm_x4(bl4, s2u(&sKl[brow * FSTR + bcol]));
                #pragma unroll
                for (int q = 0; q < 2; q++) {
                    int j = jp * 2 + q;
                    mma16816(s_[j], ah4, bh4[2 * q], bh4[2 * q + 1]);
                    mma16816(s_[j], ah4, bl4[2 * q], bl4[2 * q + 1]);
                    mma16816(s_[j], al4, bh4[2 * q], bh4[2 * q + 1]);
                }
            }
        }
        float t0 = -1e30f, t1 = -1e30f;
        #pragma unroll
        for (int j = 0; j < 8; j++) {
            s_[j][0] *= scl; s_[j][1] *= scl; s_[j][2] *= scl; s_[j][3] *= scl;
            t0 = fmaxf(t0, fmaxf(s_[j][0], s_[j][1]));
            t1 = fmaxf(t1, fmaxf(s_[j][2], s_[j][3]));
        }
        t0 = fmaxf(t0, __shfl_xor_sync(0xffffffffu, t0, 1));
        t0 = fmaxf(t0, __shfl_xor_sync(0xffffffffu, t0, 2));
        t1 = fmaxf(t1, __shfl_xor_sync(0xffffffffu, t1, 1));
        t1 = fmaxf(t1, __shfl_xor_sync(0xffffffffu, t1, 2));
        float nm0 = fmaxf(m0, t0), nm1 = fmaxf(m1, t1);
        float corr0 = __expf(m0 - nm0), corr1 = __expf(m1 - nm1);
        m0 = nm0; m1 = nm1;
        float sum0 = 0.f, sum1 = 0.f;
        #pragma unroll
        for (int j = 0; j < 8; j++) {
            s_[j][0] = __expf(s_[j][0] - m0);
            s_[j][1] = __expf(s_[j][1] - m0);
            s_[j][2] = __expf(s_[j][2] - m1);
            s_[j][3] = __expf(s_[j][3] - m1);
            sum0 += s_[j][0] + s_[j][1];
            sum1 += s_[j][2] + s_[j][3];
        }
        sum0 += __shfl_xor_sync(0xffffffffu, sum0, 1);
        sum0 += __shfl_xor_sync(0xffffffffu, sum0, 2);
        sum1 += __shfl_xor_sync(0xffffffffu, sum1, 1);
        sum1 += __shfl_xor_sync(0xffffffffu, sum1, 2);
        l0 = l0 * corr0 + sum0;
        l1 = l1 * corr1 + sum1;
        #pragma unroll
        for (int n = 0; n < 8; n++) {
            acc_o[n][0] *= corr0; acc_o[n][1] *= corr0;
            acc_o[n][2] *= corr1; acc_o[n][3] *= corr1;
        }
        #pragma unroll
        for (int t = 0; t < 4; t++) {
            u32 pah[4], pal[4];
            split2(s_[2 * t][0],     s_[2 * t][1],     pah[0], pal[0]);
            split2(s_[2 * t][2],     s_[2 * t][3],     pah[1], pal[1]);
            split2(s_[2 * t + 1][0], s_[2 * t + 1][1], pah[2], pal[2]);
            split2(s_[2 * t + 1][2], s_[2 * t + 1][3], pah[3], pal[3]);
            int vrow = t * 16 + (lane & 15);
            #pragma unroll
            for (int np = 0; np < 4; np++) {
                int vcol = (np * 2 + (lane >> 4)) * 8;
                u32 bh4[4], bl4[4];
                ldsm_x4t(bh4, s2u(&sVh[vrow * FSTR + vcol]));
                ldsm_x4t(bl4, s2u(&sVl[vrow * FSTR + vcol]));
                #pragma unroll
                for (int q = 0; q < 2; q++) {
                    int n = np * 2 + q;
                    mma16816(acc_o[n], pah, bh4[2 * q], bh4[2 * q + 1]);
                    mma16816(acc_o[n], pah, bl4[2 * q], bl4[2 * q + 1]);
                    mma16816(acc_o[n], pal, bh4[2 * q], bh4[2 * q + 1]);
                }
            }
        }
        __syncthreads();
    }

    float inv0 = 1.f / l0, inv1 = 1.f / l1;
    int r0 = q0 + w * 16 + grp;
    #pragma unroll
    for (int n = 0; n < 8; n++) {
        int col = h * DD + n * 8 + qd * 2;
        {
            long off = obase + (long)r0 * EE + col;
            u32 hp, lp;
            split2(acc_o[n][0] * inv0, acc_o[n][1] * inv0, hp, lp);
            *(u32*)&Oh[off] = hp;
            *(u32*)&Ol[off] = lp;
        }
        {
            long off = obase + (long)(r0 + 8) * EE + col;
            u32 hp, lp;
            split2(acc_o[n][2] * inv1, acc_o[n][3] * inv1, hp, lp);
            *(u32*)&Oh[off] = hp;
            *(u32*)&Ol[off] = lp;
        }
    }
}

// ------------------------- ONE-launch preprocessing -------------------------
__global__ void prep_k(const float* __restrict__ qw, const float* __restrict__ kw,
                       const float* __restrict__ vw, const float* __restrict__ ow,
                       const float* __restrict__ w1, const float* __restrict__ w2,
                       const float* __restrict__ qb, const float* __restrict__ kb,
                       const float* __restrict__ vb,
                       const float* __restrict__ in0, const float* __restrict__ in1)
{
    int t = blockIdx.x;
    int tx = threadIdx.x, ty = threadIdx.y;
    int ltid = ty * 32 + tx;

    if (t >= 8200) {
        int idx = t - 8200;
        int strm = idx >> 11;
        long i = (long)(idx & 2047) * 1024 + ltid * 4;
        const float* x = strm ? in1 : in0;
        float4 v = *(const float4*)(x + i);
        u32 hp[2], lp[2];
        split2(v.x, v.y, hp[0], lp[0]);
        split2(v.z, v.w, hp[1], lp[1]);
        long o = (long)strm * TOKE + i;
        *(uint2*)(g_xh + o) = make_uint2(hp[0], hp[1]);
        *(uint2*)(g_xl + o) = make_uint2(lp[0], lp[1]);
        return;
    }
    if (t >= 8192) {
        int blk = t - 8192;
        int i = blk >> 1;
        int tt = (blk & 1) * 256 + ltid;
        g_qkvb[i * NQKV + tt]        = qb[i * EE + tt];
        g_qkvb[i * NQKV + 512 + tt]  = kb[i * EE + tt];
        g_qkvb[i * NQKV + 1024 + tt] = vb[i * EE + tt];
        return;
    }

    __shared__ float sm[32][33];
    const float* src;
    bf *dh, *dl;
    int lds, ldd, ry, cx;

    if (t < 4096) {
        int g = t >> 10, rem = t & 1023;
        int b = rem >> 8, tt = rem & 255;
        ry = tt >> 4; cx = tt & 15;
        lds = 512; ldd = 512;
        const float* s4 = (g == 0) ? qw : (g == 1) ? kw : (g == 2) ? vw : ow;
        src = s4 + (long)b * WEE_B;
        if (g < 3) {
            dh = g_wqkvh + (long)b * WQKV_B + (long)g * 512 * EE;
            dl = g_wqkvl + (long)b * WQKV_B + (long)g * 512 * EE;
        } else {
            dh = g_owth + (long)b * WEE_B;
            dl = g_owtl + (long)b * WEE_B;
        }
    } else if (t < 6144) {
        int t2 = t - 4096;
        int b = t2 >> 10, tt = t2 & 1023;
        ry = tt >> 6; cx = tt & 63;
        lds = 2048; ldd = 512;
        src = w1 + (long)b * WFF_B;
        dh = g_w1th + (long)b * WFF_B;
        dl = g_w1tl + (long)b * WFF_B;
    } else {
        int t3 = t - 6144;
        int b = t3 >> 10, tt = t3 & 1023;
        ry = tt >> 4; cx = tt & 15;
        lds = 512; ldd = 2048;
        src = w2 + (long)b * WFF_B;
        dh = g_w2th + (long)b * WFF_B;
        dl = g_w2tl + (long)b * WFF_B;
    }

    int r0 = ry * 32, c0 = cx * 32;
    #pragma unroll
    for (int i = 0; i < 4; i++)
        sm[ty + 8 * i][tx] = src[(long)(r0 + ty + 8 * i) * lds + c0 + tx];
    __syncthreads();
    #pragma unroll
    for (int i = 0; i < 4; i++) {
        int n = c0 + ty + 8 * i, k = r0 + tx;
        float v = sm[tx][ty + 8 * i];
        bf hv = __float2bfloat16(v);
        bf lv = __float2bfloat16(v - __bfloat162float(hv));
        dh[(long)n * ldd + k] = hv;
        dl[(long)n * ldd + k] = lv;
    }
}

// ------------------------- batched residual + layernorm (+ optional split out) -----
__global__ void ln2_k(const float* __restrict__ x0, const float* __restrict__ x1,
                      const float* __restrict__ res,
                      const float* __restrict__ g0, const float* __restrict__ b0_,
                      const float* __restrict__ g1, const float* __restrict__ b1_,
                      float* __restrict__ out,
                      bf* __restrict__ oh = nullptr,
                      bf* __restrict__ ol = nullptr)
{
    long row = blockIdx.x;
    int strm = row >= NTOK;
    long r = row - (long)strm * NTOK;
    const float* x = (strm ? x1 : x0) + r * EE;
    const float* gamma = strm ? g1 : g0;
    const float* beta  = strm ? b1_ : b0_;
    int t = threadIdx.x;
    float4 v = ((const float4*)x)[t];
    if (res) {
        float4 rr = ((const float4*)(res + row * EE))[t];
        v.x += rr.x; v.y += rr.y; v.z += rr.z; v.w += rr.w;
    }
    float s = v.x + v.y + v.z + v.w;
    float q = v.x * v.x + v.y * v.y + v.z * v.z + v.w * v.w;
    #pragma unroll
    for (int o = 16; o; o >>= 1) {
        s += __shfl_xor_sync(0xffffffffu, s, o);
        q += __shfl_xor_sync(0xffffffffu, q, o);
    }
    __shared__ float shS[4], shQ[4];
    int w = t >> 5;
    if ((t & 31) == 0) { shS[w] = s; shQ[w] = q; }
    __syncthreads();
    s = shS[0] + shS[1] + shS[2] + shS[3];
    q = shQ[0] + shQ[1] + shQ[2] + shQ[3];
    float mean = s * (1.f / EE);
    float var = q * (1.f / EE) - mean * mean;
    float rstd = rsqrtf(var + 1e-5f);
    float4 g = ((const float4*)gamma)[t];
    float4 b = ((const float4*)beta)[t];
    float4 o;
    o.x = (v.x - mean) * rstd * g.x + b.x;
    o.y = (v.y - mean) * rstd * g.y + b.y;
    o.z = (v.z - mean) * rstd * g.z + b.z;
    o.w = (v.w - mean) * rstd * g.w + b.w;
    ((float4*)(out + row * EE))[t] = o;
    if (oh) {
        u32 hp[2], lp[2];
        split2(o.x, o.y, hp[0], lp[0]);
        split2(o.z, o.w, hp[1], lp[1]);
        *(uint2*)(oh + row * EE + t * 4) = make_uint2(hp[0], hp[1]);
        *(uint2*)(ol + row * EE + t * 4) = make_uint2(lp[0], lp[1]);
    }
}

// ------------------------- fused gate + mix + norm2 (gamma shared) -------------------------
__global__ void gate_mix_ln_k(const float* __restrict__ x, const float* __restrict__ cr,
                              const float* __restrict__ gw, const float* __restrict__ gb,
                              const float* __restrict__ gamma, const float* __restrict__ beta,
                              float* __restrict__ out,
                              bf* __restrict__ oh, bf* __restrict__ ol)
{
    long row = blockIdx.x;
    int t = threadIdx.x;
    float4 xv = ((const float4*)(x + row * EE))[t];
    float4 cv = ((const float4*)(cr + row * EE))[t];
    int k0 = t * 4;
    float l0 = 0.f, l1 = 0.f;
    float xs[4] = {xv.x, xv.y, xv.z, xv.w};
    float cs[4] = {cv.x, cv.y, cv.z, cv.w};
    #pragma unroll
    for (int e = 0; e < 4; e++) {
        int k = k0 + e;
        l0 += xs[e] * gw[k * 2 + 0] + cs[e] * gw[(EE + k) * 2 + 0];
        l1 += xs[e] * gw[k * 2 + 1] + cs[e] * gw[(EE + k) * 2 + 1];
    }
    #pragma unroll
    for (int o = 16; o; o >>= 1) {
        l0 += __shfl_xor_sync(0xffffffffu, l0, o);
        l1 += __shfl_xor_sync(0xffffffffu, l1, o);
    }
    __shared__ float sh0[4], sh1[4];
    int w = t >> 5;
    if ((t & 31) == 0) { sh0[w] = l0; sh1[w] = l1; }
    __syncthreads();
    l0 = sh0[0] + sh0[1] + sh0[2] + sh0[3] + gb[0];
    l1 = sh1[0] + sh1[1] + sh1[2] + sh1[3] + gb[1];
    float mx = fmaxf(l0, l1);
    float e0 = __expf(l0 - mx), e1 = __expf(l1 - mx);
    float gg0 = e0 / (e0 + e1), gg1 = e1 / (e0 + e1);
    float4 v;
    v.x = xv.x * gg0 + cv.x * gg1;
    v.y = xv.y * gg0 + cv.y * gg1;
    v.z = xv.z * gg0 + cv.z * gg1;
    v.w = xv.w * gg0 + cv.w * gg1;

    float s = v.x + v.y + v.z + v.w;
    float q = v.x * v.x + v.y * v.y + v.z * v.z + v.w * v.w;
    #pragma unroll
    for (int o = 16; o; o >>= 1) {
        s += __shfl_xor_sync(0xffffffffu, s, o);
        q += __shfl_xor_sync(0xffffffffu, q, o);
    }
    __syncthreads();
    if ((t & 31) == 0) { sh0[w] = s; sh1[w] = q; }
    __syncthreads();
    s = sh0[0] + sh0[1] + sh0[2] + sh0[3];
    q = sh1[0] + sh1[1] + sh1[2] + sh1[3];
    float mean = s * (1.f / EE);
    float var = q * (1.f / EE) - mean * mean;
    float rstd = rsqrtf(var + 1e-5f);
    float4 g = ((const float4*)gamma)[t];
    float4 b = ((const float4*)beta)[t];
    float4 o;
    o.x = (v.x - mean) * rstd * g.x + b.x;
    o.y = (v.y - mean) * rstd * g.y + b.y;
    o.z = (v.z - mean) * rstd * g.z + b.z;
    o.w = (v.w - mean) * rstd * g.w + b.w;
    ((float4*)(out + row * EE))[t] = o;
    u32 hp[2], lp[2];
    split2(o.x, o.y, hp[0], lp[0]);
    split2(o.z, o.w, hp[1], lp[1]);
    *(uint2*)(oh + row * EE + t * 4) = make_uint2(hp[0], hp[1]);
    *(uint2*)(ol + row * EE + t * 4) = make_uint2(lp[0], lp[1]);
}

// ------------------------- host orchestration -------------------------
static float* sym(const void* s) { void* p = nullptr; cudaGetSymbolAddress(&p, s); return (float*)p; }
static bf* symb(const void* s)   { void* p = nullptr; cudaGetSymbolAddress(&p, s); return (bf*)p; }

#define SMEM64 ((2 * 128 * 40 + 2 * 128 * 40) * 2 * 2)   // 81920 B
#define JBIG (1 << 30)

static void bg_f32(const bf* ah, const bf* al, const bf* bh, const bf* bl, long aB, long bB,
                   const float* bias, long biasB, float* C, long cB, int M, int N, int K, int ldc) {
    dim3 grid(N / 128, M / 128, 2);
    gemm_mma<64, 0, false><<<grid, 256, SMEM64>>>(ah, al, bh, bl, bias, C, nullptr, nullptr,
        K, K, K, ldc, aB, bB, cB, biasB, JBIG, 0, 0);
}
static void bg_sp(const bf* ah, const bf* al, const bf* bh, const bf* bl, long aB, long bB,
                  const float* bias, long biasB, bf* Ch, bf* Cl, long cB,
                  int M, int N, int K, int ldc, bool gelu,
                  int jsplit = JBIG, long aOff2 = 0, long aB2 = 0) {
    dim3 grid(N / 128, M / 128, 2);
    if (gelu)
        gemm_mma<64, 2, true><<<grid, 256, SMEM64>>>(ah, al, bh, bl, bias, nullptr, Ch, Cl,
            K, K, K, ldc, aB, bB, cB, biasB, jsplit, aOff2, aB2);
    else
        gemm_mma<64, 2, false><<<grid, 256, SMEM64>>>(ah, al, bh, bl, bias, nullptr, Ch, Cl,
            K, K, K, ldc, aB, bB, cB, biasB, jsplit, aOff2, aB2);
}

extern "C" void kernel_launch(void* const* d_in, const int* in_sizes, int n_in,
                              void* d_out, int out_size)
{
    const float* body_feats = (const float*)d_in[0];
    const float* limb_feats = (const float*)d_in[1];
    const float* attn_qw = (const float*)d_in[2];
    const float* attn_qb = (const float*)d_in[3];
    const float* attn_kw = (const float*)d_in[4];
    const float* attn_kb = (const float*)d_in[5];
    const float* attn_vw = (const float*)d_in[6];
    const float* attn_vb = (const float*)d_in[7];
    const float* attn_ow = (const float*)d_in[8];
    const float* attn_ob = (const float*)d_in[9];
    const float* ffn_w1 = (const float*)d_in[10];
    const float* ffn_b1 = (const float*)d_in[11];
    const float* ffn_w2 = (const float*)d_in[12];
    const float* ffn_b2 = (const float*)d_in[13];
    const float* nsc = (const float*)d_in[14];
    const float* nbi = (const float*)d_in[15];
    const float* gw = (const float*)d_in[16];
    const float* gb = (const float*)d_in[17];
    const unsigned* temp = (const unsigned*)d_in[18];

    cudaFuncSetAttribute(gemm_mma<64, 0, false>, cudaFuncAttributeMaxDynamicSharedMemorySize, SMEM64);
    cudaFuncSetAttribute(gemm_mma<64, 2, false>, cudaFuncAttributeMaxDynamicSharedMemorySize, SMEM64);
    cudaFuncSetAttribute(gemm_mma<64, 2, true>,  cudaFuncAttributeMaxDynamicSharedMemorySize, SMEM64);
    cudaFuncSetAttribute(flash_k, cudaFuncAttributeMaxDynamicSharedMemorySize, FSMEM);

    float* out = (float*)d_out;

    float* tmp  = sym(g_tmp);
    float* bl   = sym(g_bl);
    float* cross = sym(g_cross);
    float* ffn  = sym(g_ffn);
    bf *xh = symb(g_xh), *xl = symb(g_xl);
    bf *s1h = symb(g_s1h), *s1l = symb(g_s1l);
    bf *qkvh = symb(g_qkvh), *qkvl = symb(g_qkvl);
    bf *atth = symb(g_atth), *attl = symb(g_attl);
    bf *hidh = symb(g_hidh), *hidl = symb(g_hidl);
    bf *wqh = symb(g_wqkvh), *wql = symb(g_wqkvl);
    bf *owh = symb(g_owth), *owl = symb(g_owtl);
    bf *w1h = symb(g_w1th), *w1l = symb(g_w1tl);
    bf *w2h = symb(g_w2th), *w2l = symb(g_w2tl);
    const float* qkvb = sym(g_qkvb);

    // ---- preprocessing (ONE launch) ----
    prep_k<<<12296, dim3(32, 8)>>>(attn_qw, attn_kw, attn_vw, attn_ow, ffn_w1, ffn_w2,
                                   attn_qb, attn_kb, attn_vb, body_feats, limb_feats);

    // ---- self attention (batched over body/limb) ----
    bg_sp(xh, xl, wqh, wql, TOKE, WQKV_B, qkvb, NQKV,
          qkvh, qkvl, QKV_B, NTOK, NQKV, EE, NQKV, false);
    flash_k<<<dim3(SS / 128, 2 * NB), 256, FSMEM>>>(qkvh, qkvl, atth, attl, temp);
    bg_f32(atth, attl, owh, owl, TOKE, WEE_B, attn_ob, EE, tmp, TOKE, NTOK, EE, EE, EE);

    // norm1 (batched): body gamma 0, limb gamma 3
    ln2_k<<<2 * NTOK, 128>>>(body_feats, limb_feats, tmp,
                             nsc + 0 * EE, nbi + 0 * EE, nsc + 3 * EE, nbi + 3 * EE,
                             bl, s1h, s1l);

    // ---- cross attention: ONE fused QKV launch ----
    bg_sp(s1h, s1l, wqh + 2 * WQKV_B, wql + 2 * WQKV_B, TOKE, WQKV_B,
          qkvb + 2 * NQKV, NQKV, qkvh, qkvl, QKV_B, NTOK, NQKV, EE, NQKV, false,
          /*jsplit=*/512, /*aOff2=*/TOKE, /*aB2=*/-TOKE);
    flash_k<<<dim3(SS / 128, 2 * NB), 256, FSMEM>>>(qkvh, qkvl, atth, attl, temp);
    bg_f32(atth, attl, owh + 2 * WEE_B, owl + 2 * WEE_B, TOKE, WEE_B,
           attn_ob + 2 * EE, EE, cross, TOKE, NTOK, EE, EE, EE);

    // ---- fused gate + mix + norm2 (gamma 1 on BOTH streams — faithful) ----
    gate_mix_ln_k<<<2 * NTOK, 128>>>(bl, cross, gw, gb,
                                     nsc + 1 * EE, nbi + 1 * EE, bl, s1h, s1l);

    // ---- FFN (batched) ----
    bg_sp(s1h, s1l, w1h, w1l, TOKE, WFF_B, ffn_b1, 4 * EE,
          hidh, hidl, HID_B, NTOK, 4 * EE, EE, 4 * EE, true);
    bg_f32(hidh, hidl, w2h, w2l, HID_B, WFF_B, ffn_b2, EE, ffn, TOKE, NTOK, EE, 4 * EE, EE);

    // final norms (batched): body gamma 2, limb gamma 5 -> out
    ln2_k<<<2 * NTOK, 128>>>(bl, bl + TOKE, ffn,
                             nsc + 2 * EE, nbi + 2 * EE, nsc + 5 * EE, nbi + 5 * EE,
                             out, nullptr, nullptr);
}